// round 13
// baseline (speedup 1.0000x reference)
#include <cuda_runtime.h>
#include <cuda_fp16.h>
#include <math.h>
#include <stdint.h>

// Problem constants
#define BB 32
#define NN_TOK 785
#define CC 512
#define NH 8
#define CH 64
#define HH 28
#define WW 28
#define PIX 784
#define MTOT (BB*NN_TOK)   // 25120
#define KK 512             // GEMM K
#define KV_CHUNKS 8
#define KV_CHUNK 99

// ---------------- scratch ----------------
__device__ float g_qkv[(size_t)MTOT * 1536];
__device__ float g_kv[BB * NH * CH * CH];
__device__ float g_kvpart[(size_t)BB * NH * KV_CHUNKS * CH * CH];
__device__ float g_sumpart[BB * NH * KV_CHUNKS * CH];
__device__ float g_vimg[(size_t)BB * CC * PIX];
__device__ float g_conv[(size_t)BB * CC * PIX];
// fp16 buffers
__device__ __half g_ahi[(size_t)MTOT * KK];
__device__ __half g_alo[(size_t)MTOT * KK];
__device__ __half g_wh[1536 * KK];
__device__ __half g_ph[512 * KK];

// ---------------- helpers ----------------
__device__ __forceinline__ uint32_t smem_u32(const void* p) {
    uint32_t a;
    asm("{ .reg .u64 t; cvta.to.shared.u64 t, %1; cvt.u32.u64 %0, t; }" : "=r"(a) : "l"(p));
    return a;
}

template<int N> __device__ __forceinline__ void cp_wait() {
    asm volatile("cp.async.wait_group %0;" :: "n"(N) : "memory");
}
__device__ __forceinline__ void cp_commit() {
    asm volatile("cp.async.commit_group;" ::: "memory");
}
__device__ __forceinline__ void cp_async16(uint32_t dst, const void* src, uint32_t src_bytes) {
    asm volatile("cp.async.cg.shared.global [%0], [%1], 16, %2;"
                 :: "r"(dst), "l"(src), "r"(src_bytes));
}

__device__ __forceinline__ void mma_f16(float* d, const uint32_t* a, const uint32_t* b) {
    asm volatile("mma.sync.aligned.m16n8k16.row.col.f32.f16.f16.f32 "
        "{%0,%1,%2,%3}, {%4,%5,%6,%7}, {%8,%9}, {%0,%1,%2,%3};"
        : "+f"(d[0]), "+f"(d[1]), "+f"(d[2]), "+f"(d[3])
        : "r"(a[0]), "r"(a[1]), "r"(a[2]), "r"(a[3]), "r"(b[0]), "r"(b[1]));
}

__device__ __forceinline__ void ldmatrix_x4(uint32_t* r, uint32_t addr) {
    asm volatile("ldmatrix.sync.aligned.m8n8.x4.shared.b16 {%0,%1,%2,%3}, [%4];"
        : "=r"(r[0]), "=r"(r[1]), "=r"(r[2]), "=r"(r[3]) : "r"(addr));
}

// ---------------- fp32 -> (hi, lo) fp16 split ----------------
__global__ void split_kernel(const float* __restrict__ in,
                             __half* __restrict__ hi,
                             __half* __restrict__ lo, int n4)
{
    int i = blockIdx.x * blockDim.x + threadIdx.x;
    if (i >= n4) return;
    float4 v = ((const float4*)in)[i];
    __half hx = __float2half_rn(v.x), hy = __float2half_rn(v.y);
    __half hz = __float2half_rn(v.z), hw = __float2half_rn(v.w);
    __half lx = __float2half_rn(v.x - __half2float(hx));
    __half ly = __float2half_rn(v.y - __half2float(hy));
    __half lz = __float2half_rn(v.z - __half2float(hz));
    __half lw = __float2half_rn(v.w - __half2float(hw));
    ((__half2*)hi)[i * 2 + 0] = __halves2half2(hx, hy);
    ((__half2*)hi)[i * 2 + 1] = __halves2half2(hz, hw);
    ((__half2*)lo)[i * 2 + 0] = __halves2half2(lx, ly);
    ((__half2*)lo)[i * 2 + 1] = __halves2half2(lz, lw);
}

// ---------------- fp32 -> fp16 convert (weights) ----------------
__global__ void cvt_kernel(const float* __restrict__ in, __half* __restrict__ out, int n4)
{
    int i = blockIdx.x * blockDim.x + threadIdx.x;
    if (i >= n4) return;
    float4 v = ((const float4*)in)[i];
    ((__half2*)out)[i * 2 + 0] = __floats2half2_rn(v.x, v.y);
    ((__half2*)out)[i * 2 + 1] = __floats2half2_rn(v.z, v.w);
}

// ---------------- mma.sync GEMM: C[M,Nw] = (Ahi+Alo)[f16] @ W[f16]^T + bias ----------------
#define Bb 128
#define BN 128
#define BK 32
#define ASTR 40
#define ARR_ELEMS (128 * ASTR)
#define STAGE_ELEMS (3 * ARR_ELEMS)
#define NSTAGE 3
#define GEMM_SMEM (NSTAGE * STAGE_ELEMS * 2)  // 92160 bytes
#define NCHUNK (KK / BK)

__global__ __launch_bounds__(256, 2) void gemm_mma_kernel(
    const __half* __restrict__ Ahi, const __half* __restrict__ Alo,
    const __half* __restrict__ W,
    const float* __restrict__ bias, float* __restrict__ C,
    int M, int Nw)
{
    extern __shared__ __half sm[];
    const uint32_t smem_base = smem_u32(sm);
    const int t = threadIdx.x;
    const int lane = t & 31;
    const int wid = t >> 5;
    const int bm = blockIdx.y * Bb;
    const int bn = blockIdx.x * BN;
    const int m_base = (wid & 1) * 64;
    const int n_base = (wid >> 1) * 32;

    const int la = lane & 7;
    const int aRowOff = m_base + la + ((lane >> 3) & 1) * 8;
    const int aColOff = (lane >> 4) * 8;
    const int bRowOff = n_base + la + ((lane >> 4) & 1) * 8;
    const int bColOff = ((lane >> 3) & 1) * 8;

    float acc[4][4][4];
    #pragma unroll
    for (int mi = 0; mi < 4; mi++)
        #pragma unroll
        for (int ni = 0; ni < 4; ni++)
            #pragma unroll
            for (int j = 0; j < 4; j++) acc[mi][ni][j] = 0.f;

    auto load_stage = [&](int stage, int k0) {
        #pragma unroll
        for (int i = 0; i < 6; i++) {
            int idx = t + i * 256;
            int arr = idx >> 9;
            int sub = idx & 511;
            int row = sub >> 2;
            int seg = sub & 3;
            const __half* src;
            uint32_t nbytes = 16;
            if (arr < 2) {
                int gr = bm + row;
                if (gr >= M) { gr = 0; nbytes = 0; }
                src = (arr == 0 ? Ahi : Alo) + (size_t)gr * KK + k0 + seg * 8;
            } else {
                src = W + (size_t)(bn + row) * KK + k0 + seg * 8;
            }
            uint32_t dst = smem_base +
                (uint32_t)(stage * STAGE_ELEMS + arr * ARR_ELEMS + row * ASTR + seg * 8) * 2;
            cp_async16(dst, src, nbytes);
        }
        cp_commit();
    };

    auto compute_stage = [&](int stage) {
        const uint32_t sbase = smem_base + (uint32_t)(stage * STAGE_ELEMS) * 2;
        const uint32_t aHiB = sbase;
        const uint32_t aLoB = sbase + (uint32_t)ARR_ELEMS * 2;
        const uint32_t bB   = sbase + (uint32_t)(2 * ARR_ELEMS) * 2;
        #pragma unroll
        for (int kk = 0; kk < BK; kk += 16) {
            uint32_t bf[4][2], ah[4][4], al[4][4];
            const uint32_t aOff = (uint32_t)(aRowOff * ASTR + aColOff + kk) * 2;
            const uint32_t bOff = (uint32_t)(bRowOff * ASTR + bColOff + kk) * 2;
            #pragma unroll
            for (int pr = 0; pr < 2; pr++) {
                uint32_t r[4];
                ldmatrix_x4(r, bB + bOff + (uint32_t)(pr * 16 * ASTR) * 2);
                bf[pr * 2][0] = r[0]; bf[pr * 2][1] = r[1];
                bf[pr * 2 + 1][0] = r[2]; bf[pr * 2 + 1][1] = r[3];
            }
            #pragma unroll
            for (int mi = 0; mi < 4; mi++)
                ldmatrix_x4(ah[mi], aHiB + aOff + (uint32_t)(mi * 16 * ASTR) * 2);
            #pragma unroll
            for (int mi = 0; mi < 4; mi++)
                ldmatrix_x4(al[mi], aLoB + aOff + (uint32_t)(mi * 16 * ASTR) * 2);
            // All hi-pass MMAs first (16 independent accumulators), then lo-pass:
            // avoids back-to-back HMMA on the same accumulator (RAW stall).
            #pragma unroll
            for (int mi = 0; mi < 4; mi++)
                #pragma unroll
                for (int ni = 0; ni < 4; ni++)
                    mma_f16(acc[mi][ni], ah[mi], bf[ni]);
            #pragma unroll
            for (int mi = 0; mi < 4; mi++)
                #pragma unroll
                for (int ni = 0; ni < 4; ni++)
                    mma_f16(acc[mi][ni], al[mi], bf[ni]);
        }
    };

    load_stage(0, 0);
    load_stage(1, BK);
    #pragma unroll 1
    for (int c = 0; c < NCHUNK; c++) {
        if (c < NCHUNK - 1) cp_wait<1>(); else cp_wait<0>();
        __syncthreads();
        compute_stage(c % 3);
        if (c + 2 < NCHUNK) load_stage((c + 2) % 3, (c + 2) * BK);
    }

    #pragma unroll
    for (int mi = 0; mi < 4; mi++) {
        #pragma unroll
        for (int ni = 0; ni < 4; ni++) {
            int row = bm + m_base + mi * 16 + (lane >> 2);
            int col = bn + n_base + ni * 8 + (lane & 3) * 2;
            float2 bv = *(const float2*)(bias + col);
            if (row < M) {
                float2 o = make_float2(acc[mi][ni][0] + bv.x, acc[mi][ni][1] + bv.y);
                *(float2*)(C + (size_t)row * Nw + col) = o;
            }
            if (row + 8 < M) {
                float2 o = make_float2(acc[mi][ni][2] + bv.x, acc[mi][ni][3] + bv.y);
                *(float2*)(C + (size_t)(row + 8) * Nw + col) = o;
            }
        }
    }
}

// ---------------- fused softmax+kv partials over token chunks ----------------
__global__ __launch_bounds__(256) void kv_partial_kernel(const float* __restrict__ qkv,
                                                         float* __restrict__ kvpart,
                                                         float* __restrict__ sumpart)
{
    int bh = blockIdx.x;
    int j = blockIdx.y;
    int b = bh >> 3, head = bh & 7;
    __shared__ float Ks[32][64];
    __shared__ float Vs[32][64];
    __shared__ float part[4][64];
    int t = threadIdx.x;

    float acc[4][4];
    #pragma unroll
    for (int i = 0; i < 4; i++)
        #pragma unroll
        for (int jj = 0; jj < 4; jj++) acc[i][jj] = 0.f;
    float mysum = 0.f;

    const int rb = (t >> 4) * 4;
    const int cb = (t & 15) * 4;
    const int sr = (t >> 6) * 8;
    const int sc = t & 63;
    const float* kbase = qkv + (size_t)b * NN_TOK * 1536 + 512 + head * 64;
    const float* vbase = qkv + (size_t)b * NN_TOK * 1536 + 1024 + head * 64;
    const int nstart = j * KV_CHUNK;
    const int nend = min(nstart + KV_CHUNK, NN_TOK);

    for (int n0 = nstart; n0 < nend; n0 += 32) {
        #pragma unroll
        for (int i = 0; i < 2; i++) {
            int idx = t + i * 256;
            int nn = idx >> 4;
            int c4 = (idx & 15) * 4;
            int n = n0 + nn;
            float4 kk = make_float4(0.f, 0.f, 0.f, 0.f);
            float4 vv = make_float4(0.f, 0.f, 0.f, 0.f);
            if (n < nend) {
                kk = *(const float4*)&kbase[(size_t)n * 1536 + c4];
                vv = *(const float4*)&vbase[(size_t)n * 1536 + c4];
                kk.x = __expf(kk.x); kk.y = __expf(kk.y);
                kk.z = __expf(kk.z); kk.w = __expf(kk.w);
            }
            Ks[nn][c4 + 0] = kk.x; Ks[nn][c4 + 1] = kk.y;
            Ks[nn][c4 + 2] = kk.z; Ks[nn][c4 + 3] = kk.w;
            Vs[nn][c4 + 0] = vv.x; Vs[nn][c4 + 1] = vv.y;
            Vs[nn][c4 + 2] = vv.z; Vs[nn][c4 + 3] = vv.w;
        }
        __syncthreads();
        #pragma unroll
        for (int nn = 0; nn < 32; nn++) {
            float4 k4 = *(const float4*)&Ks[nn][rb];
            float4 v4 = *(const float4*)&Vs[nn][cb];
            float kr[4] = {k4.x, k4.y, k4.z, k4.w};
            float vr[4] = {v4.x, v4.y, v4.z, v4.w};
            #pragma unroll
            for (int i = 0; i < 4; i++)
                #pragma unroll
                for (int jj = 0; jj < 4; jj++)
                    acc[i][jj] = fmaf(kr[i], vr[jj], acc[i][jj]);
        }
        #pragma unroll
        for (int r = 0; r < 8; r++) mysum += Ks[sr + r][sc];
        __syncthreads();
    }

    part[t >> 6][sc] = mysum;
    __syncthreads();
    if (t < 64)
        sumpart[(bh * KV_CHUNKS + j) * 64 + t] =
            part[0][t] + part[1][t] + part[2][t] + part[3][t];

    float* dst = kvpart + ((size_t)(bh * KV_CHUNKS + j) * 64) * 64;
    #pragma unroll
    for (int i = 0; i < 4; i++)
        *(float4*)&dst[(rb + i) * 64 + cb] =
            make_float4(acc[i][0], acc[i][1], acc[i][2], acc[i][3]);
}

__global__ __launch_bounds__(256) void kv_reduce_kernel(const float* __restrict__ kvpart,
                                                        const float* __restrict__ sumpart,
                                                        float* __restrict__ kvout)
{
    int bh = blockIdx.x;
    int t = threadIdx.x;
    __shared__ float srcp[64];
    if (t < 64) {
        float s = 0.f;
        #pragma unroll
        for (int j = 0; j < KV_CHUNKS; j++)
            s += sumpart[(bh * KV_CHUNKS + j) * 64 + t];
        srcp[t] = 0.125f / s;
    }
    __syncthreads();
    const float* src = kvpart + (size_t)bh * KV_CHUNKS * 4096;
    #pragma unroll
    for (int i = 0; i < 16; i++) {
        int idx = t + i * 256;
        float v = 0.f;
        #pragma unroll
        for (int j = 0; j < KV_CHUNKS; j++)
            v += src[j * 4096 + idx];
        kvout[(size_t)bh * 4096 + idx] = v * srcp[idx >> 6];
    }
}

// ---------------- v transpose ----------------
__global__ void vtrans_kernel(const float* __restrict__ qkv, float* __restrict__ vimg)
{
    __shared__ float tile[32][33];
    int b = blockIdx.z;
    int c0 = blockIdx.y * 32;
    int p0 = blockIdx.x * 32;
    int tx = threadIdx.x, ty = threadIdx.y;
    #pragma unroll
    for (int i = 0; i < 4; i++) {
        int p = p0 + ty + i * 8;
        float v = 0.f;
        if (p < PIX)
            v = qkv[(size_t)(b * NN_TOK + 1 + p) * 1536 + 1024 + c0 + tx];
        tile[ty + i * 8][tx] = v;
    }
    __syncthreads();
    #pragma unroll
    for (int i = 0; i < 4; i++) {
        int c = c0 + ty + i * 8;
        int p = p0 + tx;
        if (p < PIX)
            vimg[((size_t)(b * CC + c)) * PIX + p] = tile[tx][ty + i * 8];
    }
}

// ---------------- depthwise conv ----------------
__global__ __launch_bounds__(128) void dwconv_kernel(
    const float* __restrict__ vimg,
    const float* __restrict__ w3, const float* __restrict__ b3,
    const float* __restrict__ w5, const float* __restrict__ b5,
    const float* __restrict__ w7, const float* __restrict__ b7,
    float* __restrict__ convout)
{
    int bc = blockIdx.x;
    int c = bc & 511;
    __shared__ float timg[34 * 34];
    __shared__ float wsm[49];
    int t = threadIdx.x;
    const float* img = vimg + (size_t)bc * PIX;
    for (int i = t; i < 34 * 34; i += 128) {
        int y = i / 34 - 3, x = i % 34 - 3;
        timg[i] = (y >= 0 && y < HH && x >= 0 && x < WW) ? img[y * WW + x] : 0.f;
    }
    int ks; const float* wp; float bias;
    if (c < 128)      { ks = 3; wp = w3 + c * 9;          bias = b3[c]; }
    else if (c < 320) { ks = 5; wp = w5 + (c - 128) * 25; bias = b5[c - 128]; }
    else              { ks = 7; wp = w7 + (c - 320) * 49; bias = b7[c - 320]; }
    if (t < ks * ks) wsm[t] = wp[t];
    __syncthreads();
    int pad = ks >> 1;
    for (int p = t; p < PIX; p += 128) {
        int y = p / WW, x = p % WW;
        float s = bias;
        const int base = (y + 3 - pad) * 34 + (x + 3 - pad);
        for (int ky = 0; ky < ks; ky++)
            for (int kx = 0; kx < ks; kx++)
                s = fmaf(wsm[ky * ks + kx], timg[base + ky * 34 + kx], s);
        convout[(size_t)bc * PIX + p] = s;
    }
}

// ---------------- fused factor_att + crpe + fp16 split ----------------
__global__ __launch_bounds__(256) void factor_att_fused_kernel(
    const float* __restrict__ qkv, const float* __restrict__ kv,
    const float* __restrict__ conv,
    __half* __restrict__ ahi, __half* __restrict__ alo)
{
    int bh = blockIdx.y;
    int b = bh >> 3, head = bh & 7;
    int n0 = blockIdx.x * 64;
    __shared__ float QsT[64][68];
    __shared__ float KVs[64][64];
    __shared__ float CVs[64][65];
    int t = threadIdx.x;

    #pragma unroll
    for (int i = 0; i < 4; i++) {
        int idx = t + i * 256;
        int r = idx >> 4;
        int c4 = (idx & 15) * 4;
        *(float4*)&KVs[r][c4] = *(const float4*)&kv[((size_t)bh * 64 + r) * 64 + c4];
        int n = n0 + r;
        float4 q = make_float4(0.f, 0.f, 0.f, 0.f);
        if (n < NN_TOK)
            q = *(const float4*)&qkv[(size_t)(b * NN_TOK + n) * 1536 + head * 64 + c4];
        QsT[c4 + 0][r] = q.x;
        QsT[c4 + 1][r] = q.y;
        QsT[c4 + 2][r] = q.z;
        QsT[c4 + 3][r] = q.w;
    }
    #pragma unroll
    for (int i = 0; i < 4; i++) {
        int idx = t + i * 256;
        int c = idx >> 4;
        int j4 = (idx & 15) * 4;
        const float* cbase = conv + ((size_t)(b * CC + head * 64 + c)) * PIX;
        #pragma unroll
        for (int k = 0; k < 4; k++) {
            int n = n0 + j4 + k;
            CVs[c][j4 + k] = (n >= 1 && n < NN_TOK) ? cbase[n - 1] : 0.f;
        }
    }
    __syncthreads();

    float acc[4][4];
    #pragma unroll
    for (int i = 0; i < 4; i++)
        #pragma unroll
        for (int j = 0; j < 4; j++) acc[i][j] = 0.f;

    const int rb = (t >> 4) * 4;
    const int cb = (t & 15) * 4;
    #pragma unroll 4
    for (int c = 0; c < 64; c++) {
        float4 q4 = *(const float4*)&QsT[c][rb];
        float4 kv4 = *(const float4*)&KVs[c][cb];
        float qr[4] = {q4.x, q4.y, q4.z, q4.w};
        #pragma unroll
        for (int i = 0; i < 4; i++) {
            acc[i][0] = fmaf(qr[i], kv4.x, acc[i][0]);
            acc[i][1] = fmaf(qr[i], kv4.y, acc[i][1]);
            acc[i][2] = fmaf(qr[i], kv4.z, acc[i][2]);
            acc[i][3] = fmaf(qr[i], kv4.w, acc[i][3]);
        }
    }
    #pragma unroll
    for (int i = 0; i < 4; i++) {
        int n = n0 + rb + i;
        if (n < NN_TOK) {
            size_t base = (size_t)(b * NN_TOK + n) * CC + head * 64 + cb;
            float4 q4 = *(const float4*)&qkv[(size_t)(b * NN_TOK + n) * 1536 + head * 64 + cb];
            float qv[4] = {q4.x, q4.y, q4.z, q4.w};
            __half2 h2[2], l2[2];
            #pragma unroll
            for (int j = 0; j < 4; j += 2) {
                float f0 = acc[i][j]     + qv[j]     * CVs[cb + j][rb + i];
                float f1 = acc[i][j + 1] + qv[j + 1] * CVs[cb + j + 1][rb + i];
                __half h0 = __float2half_rn(f0), h1 = __float2half_rn(f1);
                h2[j >> 1] = __halves2half2(h0, h1);
                l2[j >> 1] = __halves2half2(__float2half_rn(f0 - __half2float(h0)),
                                            __float2half_rn(f1 - __half2float(h1)));
            }
            *(__half2*)(ahi + base)     = h2[0];
            *(__half2*)(ahi + base + 2) = h2[1];
            *(__half2*)(alo + base)     = l2[0];
            *(__half2*)(alo + base + 2) = l2[1];
        }
    }
}

// ---------------- launch ----------------
extern "C" void kernel_launch(void* const* d_in, const int* in_sizes, int n_in,
                              void* d_out, int out_size)
{
    const float* x      = (const float*)d_in[0];
    const float* qkv_w  = (const float*)d_in[1];
    const float* qkv_b  = (const float*)d_in[2];
    const float* proj_w = (const float*)d_in[3];
    const float* proj_b = (const float*)d_in[4];
    const float* w3     = (const float*)d_in[5];
    const float* b3     = (const float*)d_in[6];
    const float* w5     = (const float*)d_in[7];
    const float* b5     = (const float*)d_in[8];
    const float* w7     = (const float*)d_in[9];
    const float* b7     = (const float*)d_in[10];
    float* out = (float*)d_out;

    float *qkv, *kv, *kvpart, *sumpart, *vimg, *conv;
    __half *ahi, *alo, *wh, *ph;
    cudaGetSymbolAddress((void**)&qkv,     g_qkv);
    cudaGetSymbolAddress((void**)&kv,      g_kv);
    cudaGetSymbolAddress((void**)&kvpart,  g_kvpart);
    cudaGetSymbolAddress((void**)&sumpart, g_sumpart);
    cudaGetSymbolAddress((void**)&vimg,    g_vimg);
    cudaGetSymbolAddress((void**)&conv,    g_conv);
    cudaGetSymbolAddress((void**)&ahi,     g_ahi);
    cudaGetSymbolAddress((void**)&alo,     g_alo);
    cudaGetSymbolAddress((void**)&wh,      g_wh);
    cudaGetSymbolAddress((void**)&ph,      g_ph);

    cudaFuncSetAttribute(gemm_mma_kernel,
                         cudaFuncAttributeMaxDynamicSharedMemorySize, GEMM_SMEM);

    const int M = MTOT;
    const int mtiles = (M + Bb - 1) / Bb;   // 197

    // conversions
    {
        int n4 = M * KK / 4;
        split_kernel<<<(n4 + 255) / 256, 256>>>(x, ahi, alo, n4);
        n4 = 1536 * KK / 4;
        cvt_kernel<<<(n4 + 255) / 256, 256>>>(qkv_w, wh, n4);
        n4 = 512 * KK / 4;
        cvt_kernel<<<(n4 + 255) / 256, 256>>>(proj_w, ph, n4);
    }

    // GEMM1: qkv = x @ qkv_w^T + qkv_b    [M, 1536]
    gemm_mma_kernel<<<dim3(1536 / BN, mtiles), 256, GEMM_SMEM>>>(
        ahi, alo, wh, qkv_b, qkv, M, 1536);

    // attention middle
    kv_partial_kernel<<<dim3(256, KV_CHUNKS), 256>>>(qkv, kvpart, sumpart);
    kv_reduce_kernel<<<256, 256>>>(kvpart, sumpart, kv);
    vtrans_kernel<<<dim3(25, 16, 32), dim3(32, 8)>>>(qkv, vimg);
    dwconv_kernel<<<BB * CC, 128>>>(vimg, w3, b3, w5, b5, w7, b7, conv);
    factor_att_fused_kernel<<<dim3((NN_TOK + 63) / 64, 256), 256>>>(
        qkv, kv, conv, ahi, alo);

    // GEMM2: out = att @ proj_w^T + proj_b   [M, 512]
    gemm_mma_kernel<<<dim3(512 / BN, mtiles), 256, GEMM_SMEM>>>(
        ahi, alo, ph, proj_b, out, M, 512);
}

// round 14
// speedup vs baseline: 1.5651x; 1.5651x over previous
#include <cuda_runtime.h>
#include <cuda_fp16.h>
#include <math.h>
#include <stdint.h>

// Problem constants
#define BB 32
#define NN_TOK 785
#define CC 512
#define NH 8
#define CH 64
#define HH 28
#define WW 28
#define PIX 784
#define MTOT (BB*NN_TOK)   // 25120
#define KK 512             // GEMM K
#define KV_CHUNKS 8
#define KV_CHUNK 99

// ---------------- scratch ----------------
__device__ float g_qkv[(size_t)MTOT * 1536];
__device__ float g_kv[BB * NH * CH * CH];
__device__ float g_kvpart[(size_t)BB * NH * KV_CHUNKS * CH * CH];
__device__ float g_sumpart[BB * NH * KV_CHUNKS * CH];
__device__ float g_vimg[(size_t)BB * CC * PIX];
__device__ float g_conv[(size_t)BB * CC * PIX];
// fp16 buffers
__device__ __half g_ahi[(size_t)MTOT * KK];
__device__ __half g_alo[(size_t)MTOT * KK];
__device__ __half g_wh[1536 * KK];
__device__ __half g_ph[512 * KK];

// ---------------- helpers ----------------
__device__ __forceinline__ uint32_t smem_u32(const void* p) {
    uint32_t a;
    asm("{ .reg .u64 t; cvta.to.shared.u64 t, %1; cvt.u32.u64 %0, t; }" : "=r"(a) : "l"(p));
    return a;
}

template<int N> __device__ __forceinline__ void cp_wait() {
    asm volatile("cp.async.wait_group %0;" :: "n"(N) : "memory");
}
__device__ __forceinline__ void cp_commit() {
    asm volatile("cp.async.commit_group;" ::: "memory");
}
__device__ __forceinline__ void cp_async16(uint32_t dst, const void* src, uint32_t src_bytes) {
    asm volatile("cp.async.cg.shared.global [%0], [%1], 16, %2;"
                 :: "r"(dst), "l"(src), "r"(src_bytes));
}

__device__ __forceinline__ void mma_f16(float* d, const uint32_t* a, const uint32_t* b) {
    asm volatile("mma.sync.aligned.m16n8k16.row.col.f32.f16.f16.f32 "
        "{%0,%1,%2,%3}, {%4,%5,%6,%7}, {%8,%9}, {%0,%1,%2,%3};"
        : "+f"(d[0]), "+f"(d[1]), "+f"(d[2]), "+f"(d[3])
        : "r"(a[0]), "r"(a[1]), "r"(a[2]), "r"(a[3]), "r"(b[0]), "r"(b[1]));
}

__device__ __forceinline__ void ldmatrix_x4(uint32_t* r, uint32_t addr) {
    asm volatile("ldmatrix.sync.aligned.m8n8.x4.shared.b16 {%0,%1,%2,%3}, [%4];"
        : "=r"(r[0]), "=r"(r[1]), "=r"(r[2]), "=r"(r[3]) : "r"(addr));
}

// ---------------- fp32 -> (hi, lo) fp16 split ----------------
__global__ void split_kernel(const float* __restrict__ in,
                             __half* __restrict__ hi,
                             __half* __restrict__ lo, int n4)
{
    int i = blockIdx.x * blockDim.x + threadIdx.x;
    if (i >= n4) return;
    float4 v = ((const float4*)in)[i];
    __half hx = __float2half_rn(v.x), hy = __float2half_rn(v.y);
    __half hz = __float2half_rn(v.z), hw = __float2half_rn(v.w);
    __half lx = __float2half_rn(v.x - __half2float(hx));
    __half ly = __float2half_rn(v.y - __half2float(hy));
    __half lz = __float2half_rn(v.z - __half2float(hz));
    __half lw = __float2half_rn(v.w - __half2float(hw));
    ((__half2*)hi)[i * 2 + 0] = __halves2half2(hx, hy);
    ((__half2*)hi)[i * 2 + 1] = __halves2half2(hz, hw);
    ((__half2*)lo)[i * 2 + 0] = __halves2half2(lx, ly);
    ((__half2*)lo)[i * 2 + 1] = __halves2half2(lz, lw);
}

// ---------------- fp32 -> fp16 convert (weights) ----------------
__global__ void cvt_kernel(const float* __restrict__ in, __half* __restrict__ out, int n4)
{
    int i = blockIdx.x * blockDim.x + threadIdx.x;
    if (i >= n4) return;
    float4 v = ((const float4*)in)[i];
    ((__half2*)out)[i * 2 + 0] = __floats2half2_rn(v.x, v.y);
    ((__half2*)out)[i * 2 + 1] = __floats2half2_rn(v.z, v.w);
}

// ---------------- mma.sync GEMM: C[M,Nw] = (Ahi+Alo)[f16] @ W[f16]^T + bias ----------------
#define Bb 128
#define BN 128
#define BK 32
#define ASTR 40
#define ARR_ELEMS (128 * ASTR)
#define STAGE_ELEMS (3 * ARR_ELEMS)
#define NSTAGE 3
#define GEMM_SMEM (NSTAGE * STAGE_ELEMS * 2)  // 92160 bytes
#define NCHUNK (KK / BK)

__global__ __launch_bounds__(256, 2) void gemm_mma_kernel(
    const __half* __restrict__ Ahi, const __half* __restrict__ Alo,
    const __half* __restrict__ W,
    const float* __restrict__ bias, float* __restrict__ C,
    int M, int Nw)
{
    extern __shared__ __half sm[];
    const uint32_t smem_base = smem_u32(sm);
    const int t = threadIdx.x;
    const int lane = t & 31;
    const int wid = t >> 5;
    const int bm = blockIdx.y * Bb;
    const int bn = blockIdx.x * BN;
    const int m_base = (wid & 1) * 64;
    const int n_base = (wid >> 1) * 32;

    const int la = lane & 7;
    const int aRowOff = m_base + la + ((lane >> 3) & 1) * 8;
    const int aColOff = (lane >> 4) * 8;
    const int bRowOff = n_base + la + ((lane >> 4) & 1) * 8;
    const int bColOff = ((lane >> 3) & 1) * 8;

    float acc[4][4][4];
    #pragma unroll
    for (int mi = 0; mi < 4; mi++)
        #pragma unroll
        for (int ni = 0; ni < 4; ni++)
            #pragma unroll
            for (int j = 0; j < 4; j++) acc[mi][ni][j] = 0.f;

    auto load_stage = [&](int stage, int k0) {
        #pragma unroll
        for (int i = 0; i < 6; i++) {
            int idx = t + i * 256;
            int arr = idx >> 9;
            int sub = idx & 511;
            int row = sub >> 2;
            int seg = sub & 3;
            const __half* src;
            uint32_t nbytes = 16;
            if (arr < 2) {
                int gr = bm + row;
                if (gr >= M) { gr = 0; nbytes = 0; }
                src = (arr == 0 ? Ahi : Alo) + (size_t)gr * KK + k0 + seg * 8;
            } else {
                src = W + (size_t)(bn + row) * KK + k0 + seg * 8;
            }
            uint32_t dst = smem_base +
                (uint32_t)(stage * STAGE_ELEMS + arr * ARR_ELEMS + row * ASTR + seg * 8) * 2;
            cp_async16(dst, src, nbytes);
        }
        cp_commit();
    };

    auto compute_stage = [&](int stage) {
        const uint32_t sbase = smem_base + (uint32_t)(stage * STAGE_ELEMS) * 2;
        const uint32_t aHiB = sbase;
        const uint32_t aLoB = sbase + (uint32_t)ARR_ELEMS * 2;
        const uint32_t bB   = sbase + (uint32_t)(2 * ARR_ELEMS) * 2;
        #pragma unroll
        for (int kk = 0; kk < BK; kk += 16) {
            uint32_t bf[4][2], ah[4][4], al[4][4];
            const uint32_t aOff = (uint32_t)(aRowOff * ASTR + aColOff + kk) * 2;
            const uint32_t bOff = (uint32_t)(bRowOff * ASTR + bColOff + kk) * 2;
            #pragma unroll
            for (int pr = 0; pr < 2; pr++) {
                uint32_t r[4];
                ldmatrix_x4(r, bB + bOff + (uint32_t)(pr * 16 * ASTR) * 2);
                bf[pr * 2][0] = r[0]; bf[pr * 2][1] = r[1];
                bf[pr * 2 + 1][0] = r[2]; bf[pr * 2 + 1][1] = r[3];
            }
            #pragma unroll
            for (int mi = 0; mi < 4; mi++)
                ldmatrix_x4(ah[mi], aHiB + aOff + (uint32_t)(mi * 16 * ASTR) * 2);
            #pragma unroll
            for (int mi = 0; mi < 4; mi++)
                ldmatrix_x4(al[mi], aLoB + aOff + (uint32_t)(mi * 16 * ASTR) * 2);
            #pragma unroll
            for (int mi = 0; mi < 4; mi++)
                #pragma unroll
                for (int ni = 0; ni < 4; ni++)
                    mma_f16(acc[mi][ni], ah[mi], bf[ni]);
            #pragma unroll
            for (int mi = 0; mi < 4; mi++)
                #pragma unroll
                for (int ni = 0; ni < 4; ni++)
                    mma_f16(acc[mi][ni], al[mi], bf[ni]);
        }
    };

    load_stage(0, 0);
    load_stage(1, BK);
    #pragma unroll 1
    for (int c = 0; c < NCHUNK; c++) {
        if (c < NCHUNK - 1) cp_wait<1>(); else cp_wait<0>();
        __syncthreads();
        compute_stage(c % 3);
        if (c + 2 < NCHUNK) load_stage((c + 2) % 3, (c + 2) * BK);
    }

    #pragma unroll
    for (int mi = 0; mi < 4; mi++) {
        #pragma unroll
        for (int ni = 0; ni < 4; ni++) {
            int row = bm + m_base + mi * 16 + (lane >> 2);
            int col = bn + n_base + ni * 8 + (lane & 3) * 2;
            float2 bv = *(const float2*)(bias + col);
            if (row < M) {
                float2 o = make_float2(acc[mi][ni][0] + bv.x, acc[mi][ni][1] + bv.y);
                *(float2*)(C + (size_t)row * Nw + col) = o;
            }
            if (row + 8 < M) {
                float2 o = make_float2(acc[mi][ni][2] + bv.x, acc[mi][ni][3] + bv.y);
                *(float2*)(C + (size_t)(row + 8) * Nw + col) = o;
            }
        }
    }
}

// ---------------- fused softmax+kv partials + v-transpose writeout ----------------
// Each (bh, chunk) block stages K/V tiles in smem; V tiles are also written out
// transposed to vimg (each v element is staged exactly once across the grid).
__global__ __launch_bounds__(256) void kv_partial_kernel(const float* __restrict__ qkv,
                                                         float* __restrict__ kvpart,
                                                         float* __restrict__ sumpart,
                                                         float* __restrict__ vimg)
{
    int bh = blockIdx.x;
    int j = blockIdx.y;
    int b = bh >> 3, head = bh & 7;
    __shared__ float Ks[32][64];
    __shared__ float Vs[32][68];   // stride 68: float4-aligned, 4-mod-32 banks
    __shared__ float part[4][64];
    int t = threadIdx.x;

    float acc[4][4];
    #pragma unroll
    for (int i = 0; i < 4; i++)
        #pragma unroll
        for (int jj = 0; jj < 4; jj++) acc[i][jj] = 0.f;
    float mysum = 0.f;

    const int rb = (t >> 4) * 4;
    const int cb = (t & 15) * 4;
    const int sr = (t >> 6) * 8;
    const int sc = t & 63;
    const int lane = t & 31;
    const int crow = t >> 5;       // 0..7
    const float* kbase = qkv + (size_t)b * NN_TOK * 1536 + 512 + head * 64;
    const float* vbase = qkv + (size_t)b * NN_TOK * 1536 + 1024 + head * 64;
    float* vrow_base = vimg + ((size_t)(b * CC + head * 64)) * PIX;
    const int nstart = j * KV_CHUNK;
    const int nend = min(nstart + KV_CHUNK, NN_TOK);

    for (int n0 = nstart; n0 < nend; n0 += 32) {
        #pragma unroll
        for (int i = 0; i < 2; i++) {
            int idx = t + i * 256;
            int nn = idx >> 4;
            int c4 = (idx & 15) * 4;
            int n = n0 + nn;
            float4 kk = make_float4(0.f, 0.f, 0.f, 0.f);
            float4 vv = make_float4(0.f, 0.f, 0.f, 0.f);
            if (n < nend) {
                kk = *(const float4*)&kbase[(size_t)n * 1536 + c4];
                vv = *(const float4*)&vbase[(size_t)n * 1536 + c4];
                kk.x = __expf(kk.x); kk.y = __expf(kk.y);
                kk.z = __expf(kk.z); kk.w = __expf(kk.w);
            }
            Ks[nn][c4 + 0] = kk.x; Ks[nn][c4 + 1] = kk.y;
            Ks[nn][c4 + 2] = kk.z; Ks[nn][c4 + 3] = kk.w;
            Vs[nn][c4 + 0] = vv.x; Vs[nn][c4 + 1] = vv.y;
            Vs[nn][c4 + 2] = vv.z; Vs[nn][c4 + 3] = vv.w;
        }
        __syncthreads();
        #pragma unroll
        for (int nn = 0; nn < 32; nn++) {
            float4 k4 = *(const float4*)&Ks[nn][rb];
            float4 v4 = *(const float4*)&Vs[nn][cb];
            float kr[4] = {k4.x, k4.y, k4.z, k4.w};
            float vr[4] = {v4.x, v4.y, v4.z, v4.w};
            #pragma unroll
            for (int i = 0; i < 4; i++)
                #pragma unroll
                for (int jj = 0; jj < 4; jj++)
                    acc[i][jj] = fmaf(kr[i], vr[jj], acc[i][jj]);
        }
        #pragma unroll
        for (int r = 0; r < 8; r++) mysum += Ks[sr + r][sc];
        // transposed v writeout: lane-major along n -> 128B-coalesced rows
        {
            int n = n0 + lane;
            if (n >= 1 && n < nend) {
                #pragma unroll
                for (int pass = 0; pass < 8; pass++) {
                    int c = crow + pass * 8;
                    vrow_base[(size_t)c * PIX + (n - 1)] = Vs[lane][c];
                }
            }
        }
        __syncthreads();
    }

    part[t >> 6][sc] = mysum;
    __syncthreads();
    if (t < 64)
        sumpart[(bh * KV_CHUNKS + j) * 64 + t] =
            part[0][t] + part[1][t] + part[2][t] + part[3][t];

    float* dst = kvpart + ((size_t)(bh * KV_CHUNKS + j) * 64) * 64;
    #pragma unroll
    for (int i = 0; i < 4; i++)
        *(float4*)&dst[(rb + i) * 64 + cb] =
            make_float4(acc[i][0], acc[i][1], acc[i][2], acc[i][3]);
}

__global__ __launch_bounds__(256) void kv_reduce_kernel(const float* __restrict__ kvpart,
                                                        const float* __restrict__ sumpart,
                                                        float* __restrict__ kvout)
{
    int bh = blockIdx.x;
    int t = threadIdx.x;
    __shared__ float srcp[64];
    if (t < 64) {
        float s = 0.f;
        #pragma unroll
        for (int j = 0; j < KV_CHUNKS; j++)
            s += sumpart[(bh * KV_CHUNKS + j) * 64 + t];
        srcp[t] = 0.125f / s;
    }
    __syncthreads();
    const float* src = kvpart + (size_t)bh * KV_CHUNKS * 4096;
    #pragma unroll
    for (int i = 0; i < 16; i++) {
        int idx = t + i * 256;
        float v = 0.f;
        #pragma unroll
        for (int j = 0; j < KV_CHUNKS; j++)
            v += src[j * 4096 + idx];
        kvout[(size_t)bh * 4096 + idx] = v * srcp[idx >> 6];
    }
}

// ---------------- depthwise conv ----------------
__global__ __launch_bounds__(128) void dwconv_kernel(
    const float* __restrict__ vimg,
    const float* __restrict__ w3, const float* __restrict__ b3,
    const float* __restrict__ w5, const float* __restrict__ b5,
    const float* __restrict__ w7, const float* __restrict__ b7,
    float* __restrict__ convout)
{
    int bc = blockIdx.x;
    int c = bc & 511;
    __shared__ float timg[34 * 34];
    __shared__ float wsm[49];
    int t = threadIdx.x;
    const float* img = vimg + (size_t)bc * PIX;
    for (int i = t; i < 34 * 34; i += 128) {
        int y = i / 34 - 3, x = i % 34 - 3;
        timg[i] = (y >= 0 && y < HH && x >= 0 && x < WW) ? img[y * WW + x] : 0.f;
    }
    int ks; const float* wp; float bias;
    if (c < 128)      { ks = 3; wp = w3 + c * 9;          bias = b3[c]; }
    else if (c < 320) { ks = 5; wp = w5 + (c - 128) * 25; bias = b5[c - 128]; }
    else              { ks = 7; wp = w7 + (c - 320) * 49; bias = b7[c - 320]; }
    if (t < ks * ks) wsm[t] = wp[t];
    __syncthreads();
    int pad = ks >> 1;
    for (int p = t; p < PIX; p += 128) {
        int y = p / WW, x = p % WW;
        float s = bias;
        const int base = (y + 3 - pad) * 34 + (x + 3 - pad);
        for (int ky = 0; ky < ks; ky++)
            for (int kx = 0; kx < ks; kx++)
                s = fmaf(wsm[ky * ks + kx], timg[base + ky * 34 + kx], s);
        convout[(size_t)bc * PIX + p] = s;
    }
}

// ---------------- fused factor_att + crpe + fp16 split ----------------
__global__ __launch_bounds__(256) void factor_att_fused_kernel(
    const float* __restrict__ qkv, const float* __restrict__ kv,
    const float* __restrict__ conv,
    __half* __restrict__ ahi, __half* __restrict__ alo)
{
    int bh = blockIdx.y;
    int b = bh >> 3, head = bh & 7;
    int n0 = blockIdx.x * 64;
    __shared__ float QsT[64][68];
    __shared__ float KVs[64][64];
    __shared__ float CVs[64][65];
    int t = threadIdx.x;

    #pragma unroll
    for (int i = 0; i < 4; i++) {
        int idx = t + i * 256;
        int r = idx >> 4;
        int c4 = (idx & 15) * 4;
        *(float4*)&KVs[r][c4] = *(const float4*)&kv[((size_t)bh * 64 + r) * 64 + c4];
        int n = n0 + r;
        float4 q = make_float4(0.f, 0.f, 0.f, 0.f);
        if (n < NN_TOK)
            q = *(const float4*)&qkv[(size_t)(b * NN_TOK + n) * 1536 + head * 64 + c4];
        QsT[c4 + 0][r] = q.x;
        QsT[c4 + 1][r] = q.y;
        QsT[c4 + 2][r] = q.z;
        QsT[c4 + 3][r] = q.w;
    }
    #pragma unroll
    for (int i = 0; i < 4; i++) {
        int idx = t + i * 256;
        int c = idx >> 4;
        int j4 = (idx & 15) * 4;
        const float* cbase = conv + ((size_t)(b * CC + head * 64 + c)) * PIX;
        #pragma unroll
        for (int k = 0; k < 4; k++) {
            int n = n0 + j4 + k;
            CVs[c][j4 + k] = (n >= 1 && n < NN_TOK) ? cbase[n - 1] : 0.f;
        }
    }
    __syncthreads();

    float acc[4][4];
    #pragma unroll
    for (int i = 0; i < 4; i++)
        #pragma unroll
        for (int j = 0; j < 4; j++) acc[i][j] = 0.f;

    const int rb = (t >> 4) * 4;
    const int cb = (t & 15) * 4;
    #pragma unroll 4
    for (int c = 0; c < 64; c++) {
        float4 q4 = *(const float4*)&QsT[c][rb];
        float4 kv4 = *(const float4*)&KVs[c][cb];
        float qr[4] = {q4.x, q4.y, q4.z, q4.w};
        #pragma unroll
        for (int i = 0; i < 4; i++) {
            acc[i][0] = fmaf(qr[i], kv4.x, acc[i][0]);
            acc[i][1] = fmaf(qr[i], kv4.y, acc[i][1]);
            acc[i][2] = fmaf(qr[i], kv4.z, acc[i][2]);
            acc[i][3] = fmaf(qr[i], kv4.w, acc[i][3]);
        }
    }
    #pragma unroll
    for (int i = 0; i < 4; i++) {
        int n = n0 + rb + i;
        if (n < NN_TOK) {
            size_t base = (size_t)(b * NN_TOK + n) * CC + head * 64 + cb;
            float4 q4 = *(const float4*)&qkv[(size_t)(b * NN_TOK + n) * 1536 + head * 64 + cb];
            float qv[4] = {q4.x, q4.y, q4.z, q4.w};
            __half2 h2[2], l2[2];
            #pragma unroll
            for (int j = 0; j < 4; j += 2) {
                float f0 = acc[i][j]     + qv[j]     * CVs[cb + j][rb + i];
                float f1 = acc[i][j + 1] + qv[j + 1] * CVs[cb + j + 1][rb + i];
                __half h0 = __float2half_rn(f0), h1 = __float2half_rn(f1);
                h2[j >> 1] = __halves2half2(h0, h1);
                l2[j >> 1] = __halves2half2(__float2half_rn(f0 - __half2float(h0)),
                                            __float2half_rn(f1 - __half2float(h1)));
            }
            *(__half2*)(ahi + base)     = h2[0];
            *(__half2*)(ahi + base + 2) = h2[1];
            *(__half2*)(alo + base)     = l2[0];
            *(__half2*)(alo + base + 2) = l2[1];
        }
    }
}

// ---------------- launch ----------------
extern "C" void kernel_launch(void* const* d_in, const int* in_sizes, int n_in,
                              void* d_out, int out_size)
{
    const float* x      = (const float*)d_in[0];
    const float* qkv_w  = (const float*)d_in[1];
    const float* qkv_b  = (const float*)d_in[2];
    const float* proj_w = (const float*)d_in[3];
    const float* proj_b = (const float*)d_in[4];
    const float* w3     = (const float*)d_in[5];
    const float* b3     = (const float*)d_in[6];
    const float* w5     = (const float*)d_in[7];
    const float* b5     = (const float*)d_in[8];
    const float* w7     = (const float*)d_in[9];
    const float* b7     = (const float*)d_in[10];
    float* out = (float*)d_out;

    float *qkv, *kv, *kvpart, *sumpart, *vimg, *conv;
    __half *ahi, *alo, *wh, *ph;
    cudaGetSymbolAddress((void**)&qkv,     g_qkv);
    cudaGetSymbolAddress((void**)&kv,      g_kv);
    cudaGetSymbolAddress((void**)&kvpart,  g_kvpart);
    cudaGetSymbolAddress((void**)&sumpart, g_sumpart);
    cudaGetSymbolAddress((void**)&vimg,    g_vimg);
    cudaGetSymbolAddress((void**)&conv,    g_conv);
    cudaGetSymbolAddress((void**)&ahi,     g_ahi);
    cudaGetSymbolAddress((void**)&alo,     g_alo);
    cudaGetSymbolAddress((void**)&wh,      g_wh);
    cudaGetSymbolAddress((void**)&ph,      g_ph);

    cudaFuncSetAttribute(gemm_mma_kernel,
                         cudaFuncAttributeMaxDynamicSharedMemorySize, GEMM_SMEM);

    const int M = MTOT;
    const int mtiles = (M + Bb - 1) / Bb;   // 197

    // conversions
    {
        int n4 = M * KK / 4;
        split_kernel<<<(n4 + 255) / 256, 256>>>(x, ahi, alo, n4);
        n4 = 1536 * KK / 4;
        cvt_kernel<<<(n4 + 255) / 256, 256>>>(qkv_w, wh, n4);
        n4 = 512 * KK / 4;
        cvt_kernel<<<(n4 + 255) / 256, 256>>>(proj_w, ph, n4);
    }

    // GEMM1: qkv = x @ qkv_w^T + qkv_b    [M, 1536]
    gemm_mma_kernel<<<dim3(1536 / BN, mtiles), 256, GEMM_SMEM>>>(
        ahi, alo, wh, qkv_b, qkv, M, 1536);

    // attention middle (kv partials also emit transposed v)
    kv_partial_kernel<<<dim3(256, KV_CHUNKS), 256>>>(qkv, kvpart, sumpart, vimg);
    kv_reduce_kernel<<<256, 256>>>(kvpart, sumpart, kv);
    dwconv_kernel<<<BB * CC, 128>>>(vimg, w3, b3, w5, b5, w7, b7, conv);
    factor_att_fused_kernel<<<dim3((NN_TOK + 63) / 64, 256), 256>>>(
        qkv, kv, conv, ahi, alo);

    // GEMM2: out = att @ proj_w^T + proj_b   [M, 512]
    gemm_mma_kernel<<<dim3(512 / BN, mtiles), 256, GEMM_SMEM>>>(
        ahi, alo, ph, proj_b, out, M, 512);
}

// round 15
// speedup vs baseline: 1.6057x; 1.0260x over previous
#include <cuda_runtime.h>
#include <cuda_fp16.h>
#include <math.h>
#include <stdint.h>

// Problem constants
#define BB 32
#define NN_TOK 785
#define CC 512
#define NH 8
#define CH 64
#define HH 28
#define WW 28
#define PIX 784
#define MTOT (BB*NN_TOK)   // 25120
#define KK 512             // GEMM K
#define KV_CHUNKS 8
#define KV_CHUNK 99

// ---------------- scratch ----------------
__device__ float g_qkv[(size_t)MTOT * 1536];
__device__ float g_kv[BB * NH * CH * CH];
__device__ float g_kvpart[(size_t)BB * NH * KV_CHUNKS * CH * CH];
__device__ float g_sumpart[BB * NH * KV_CHUNKS * CH];
__device__ float g_vimg[(size_t)BB * CC * PIX];
__device__ float g_conv[(size_t)BB * CC * PIX];
// fp16 buffers
__device__ __half g_ahi[(size_t)MTOT * KK];
__device__ __half g_alo[(size_t)MTOT * KK];
__device__ __half g_wh[1536 * KK];
__device__ __half g_ph[512 * KK];

// ---------------- helpers ----------------
__device__ __forceinline__ uint32_t smem_u32(const void* p) {
    uint32_t a;
    asm("{ .reg .u64 t; cvta.to.shared.u64 t, %1; cvt.u32.u64 %0, t; }" : "=r"(a) : "l"(p));
    return a;
}

template<int N> __device__ __forceinline__ void cp_wait() {
    asm volatile("cp.async.wait_group %0;" :: "n"(N) : "memory");
}
__device__ __forceinline__ void cp_commit() {
    asm volatile("cp.async.commit_group;" ::: "memory");
}
__device__ __forceinline__ void cp_async16(uint32_t dst, const void* src, uint32_t src_bytes) {
    asm volatile("cp.async.cg.shared.global [%0], [%1], 16, %2;"
                 :: "r"(dst), "l"(src), "r"(src_bytes));
}

__device__ __forceinline__ void mma_f16(float* d, const uint32_t* a, const uint32_t* b) {
    asm volatile("mma.sync.aligned.m16n8k16.row.col.f32.f16.f16.f32 "
        "{%0,%1,%2,%3}, {%4,%5,%6,%7}, {%8,%9}, {%0,%1,%2,%3};"
        : "+f"(d[0]), "+f"(d[1]), "+f"(d[2]), "+f"(d[3])
        : "r"(a[0]), "r"(a[1]), "r"(a[2]), "r"(a[3]), "r"(b[0]), "r"(b[1]));
}

__device__ __forceinline__ void ldmatrix_x4(uint32_t* r, uint32_t addr) {
    asm volatile("ldmatrix.sync.aligned.m8n8.x4.shared.b16 {%0,%1,%2,%3}, [%4];"
        : "=r"(r[0]), "=r"(r[1]), "=r"(r[2]), "=r"(r[3]) : "r"(addr));
}

// ---------------- fp32 -> (hi, lo) fp16 split ----------------
__global__ void split_kernel(const float* __restrict__ in,
                             __half* __restrict__ hi,
                             __half* __restrict__ lo, int n4)
{
    int i = blockIdx.x * blockDim.x + threadIdx.x;
    if (i >= n4) return;
    float4 v = ((const float4*)in)[i];
    __half hx = __float2half_rn(v.x), hy = __float2half_rn(v.y);
    __half hz = __float2half_rn(v.z), hw = __float2half_rn(v.w);
    __half lx = __float2half_rn(v.x - __half2float(hx));
    __half ly = __float2half_rn(v.y - __half2float(hy));
    __half lz = __float2half_rn(v.z - __half2float(hz));
    __half lw = __float2half_rn(v.w - __half2float(hw));
    ((__half2*)hi)[i * 2 + 0] = __halves2half2(hx, hy);
    ((__half2*)hi)[i * 2 + 1] = __halves2half2(hz, hw);
    ((__half2*)lo)[i * 2 + 0] = __halves2half2(lx, ly);
    ((__half2*)lo)[i * 2 + 1] = __halves2half2(lz, lw);
}

// ---------------- fp32 -> fp16 convert (weights) ----------------
__global__ void cvt_kernel(const float* __restrict__ in, __half* __restrict__ out, int n4)
{
    int i = blockIdx.x * blockDim.x + threadIdx.x;
    if (i >= n4) return;
    float4 v = ((const float4*)in)[i];
    ((__half2*)out)[i * 2 + 0] = __floats2half2_rn(v.x, v.y);
    ((__half2*)out)[i * 2 + 1] = __floats2half2_rn(v.z, v.w);
}

// ---------------- mma.sync GEMM: C[M,Nw] = (Ahi+Alo)[f16] @ W[f16]^T + bias ----------------
// Warp tile 32x64 (mi=2, ni=8): 8 ldmatrix per 32 MMAs (vs 10 for 64x32).
#define Bb 128
#define BN 128
#define BK 32
#define ASTR 40
#define ARR_ELEMS (128 * ASTR)
#define STAGE_ELEMS (3 * ARR_ELEMS)
#define NSTAGE 3
#define GEMM_SMEM (NSTAGE * STAGE_ELEMS * 2)  // 92160 bytes
#define NCHUNK (KK / BK)

__global__ __launch_bounds__(256, 2) void gemm_mma_kernel(
    const __half* __restrict__ Ahi, const __half* __restrict__ Alo,
    const __half* __restrict__ W,
    const float* __restrict__ bias, float* __restrict__ C,
    int M, int Nw)
{
    extern __shared__ __half sm[];
    const uint32_t smem_base = smem_u32(sm);
    const int t = threadIdx.x;
    const int lane = t & 31;
    const int wid = t >> 5;
    const int bm = blockIdx.y * Bb;
    const int bn = blockIdx.x * BN;
    const int m_base = (wid & 3) * 32;   // 4 warps tile M (32 rows each)
    const int n_base = (wid >> 2) * 64;  // 2 warps tile N (64 cols each)

    const int la = lane & 7;
    const int aRowOff = m_base + la + ((lane >> 3) & 1) * 8;
    const int aColOff = (lane >> 4) * 8;
    const int bRowOff = n_base + la + ((lane >> 4) & 1) * 8;
    const int bColOff = ((lane >> 3) & 1) * 8;

    float acc[2][8][4];
    #pragma unroll
    for (int mi = 0; mi < 2; mi++)
        #pragma unroll
        for (int ni = 0; ni < 8; ni++)
            #pragma unroll
            for (int j = 0; j < 4; j++) acc[mi][ni][j] = 0.f;

    auto load_stage = [&](int stage, int k0) {
        #pragma unroll
        for (int i = 0; i < 6; i++) {
            int idx = t + i * 256;
            int arr = idx >> 9;
            int sub = idx & 511;
            int row = sub >> 2;
            int seg = sub & 3;
            const __half* src;
            uint32_t nbytes = 16;
            if (arr < 2) {
                int gr = bm + row;
                if (gr >= M) { gr = 0; nbytes = 0; }
                src = (arr == 0 ? Ahi : Alo) + (size_t)gr * KK + k0 + seg * 8;
            } else {
                src = W + (size_t)(bn + row) * KK + k0 + seg * 8;
            }
            uint32_t dst = smem_base +
                (uint32_t)(stage * STAGE_ELEMS + arr * ARR_ELEMS + row * ASTR + seg * 8) * 2;
            cp_async16(dst, src, nbytes);
        }
        cp_commit();
    };

    auto compute_stage = [&](int stage) {
        const uint32_t sbase = smem_base + (uint32_t)(stage * STAGE_ELEMS) * 2;
        const uint32_t aHiB = sbase;
        const uint32_t aLoB = sbase + (uint32_t)ARR_ELEMS * 2;
        const uint32_t bB   = sbase + (uint32_t)(2 * ARR_ELEMS) * 2;
        #pragma unroll
        for (int kk = 0; kk < BK; kk += 16) {
            uint32_t bf[8][2], ah[2][4], al[2][4];
            const uint32_t aOff = (uint32_t)(aRowOff * ASTR + aColOff + kk) * 2;
            const uint32_t bOff = (uint32_t)(bRowOff * ASTR + bColOff + kk) * 2;
            #pragma unroll
            for (int pr = 0; pr < 4; pr++) {
                uint32_t r[4];
                ldmatrix_x4(r, bB + bOff + (uint32_t)(pr * 16 * ASTR) * 2);
                bf[pr * 2][0] = r[0]; bf[pr * 2][1] = r[1];
                bf[pr * 2 + 1][0] = r[2]; bf[pr * 2 + 1][1] = r[3];
            }
            #pragma unroll
            for (int mi = 0; mi < 2; mi++)
                ldmatrix_x4(ah[mi], aHiB + aOff + (uint32_t)(mi * 16 * ASTR) * 2);
            #pragma unroll
            for (int mi = 0; mi < 2; mi++)
                ldmatrix_x4(al[mi], aLoB + aOff + (uint32_t)(mi * 16 * ASTR) * 2);
            #pragma unroll
            for (int mi = 0; mi < 2; mi++)
                #pragma unroll
                for (int ni = 0; ni < 8; ni++)
                    mma_f16(acc[mi][ni], ah[mi], bf[ni]);
            #pragma unroll
            for (int mi = 0; mi < 2; mi++)
                #pragma unroll
                for (int ni = 0; ni < 8; ni++)
                    mma_f16(acc[mi][ni], al[mi], bf[ni]);
        }
    };

    load_stage(0, 0);
    load_stage(1, BK);
    #pragma unroll 1
    for (int c = 0; c < NCHUNK; c++) {
        if (c < NCHUNK - 1) cp_wait<1>(); else cp_wait<0>();
        __syncthreads();
        compute_stage(c % 3);
        if (c + 2 < NCHUNK) load_stage((c + 2) % 3, (c + 2) * BK);
    }

    #pragma unroll
    for (int mi = 0; mi < 2; mi++) {
        #pragma unroll
        for (int ni = 0; ni < 8; ni++) {
            int row = bm + m_base + mi * 16 + (lane >> 2);
            int col = bn + n_base + ni * 8 + (lane & 3) * 2;
            float2 bv = *(const float2*)(bias + col);
            if (row < M) {
                float2 o = make_float2(acc[mi][ni][0] + bv.x, acc[mi][ni][1] + bv.y);
                *(float2*)(C + (size_t)row * Nw + col) = o;
            }
            if (row + 8 < M) {
                float2 o = make_float2(acc[mi][ni][2] + bv.x, acc[mi][ni][3] + bv.y);
                *(float2*)(C + (size_t)(row + 8) * Nw + col) = o;
            }
        }
    }
}

// ---------------- fused softmax+kv partials + v-transpose writeout ----------------
__global__ __launch_bounds__(256) void kv_partial_kernel(const float* __restrict__ qkv,
                                                         float* __restrict__ kvpart,
                                                         float* __restrict__ sumpart,
                                                         float* __restrict__ vimg)
{
    int bh = blockIdx.x;
    int j = blockIdx.y;
    int b = bh >> 3, head = bh & 7;
    __shared__ float Ks[32][64];
    __shared__ float Vs[32][68];
    __shared__ float part[4][64];
    int t = threadIdx.x;

    float acc[4][4];
    #pragma unroll
    for (int i = 0; i < 4; i++)
        #pragma unroll
        for (int jj = 0; jj < 4; jj++) acc[i][jj] = 0.f;
    float mysum = 0.f;

    const int rb = (t >> 4) * 4;
    const int cb = (t & 15) * 4;
    const int sr = (t >> 6) * 8;
    const int sc = t & 63;
    const int lane = t & 31;
    const int crow = t >> 5;
    const float* kbase = qkv + (size_t)b * NN_TOK * 1536 + 512 + head * 64;
    const float* vbase = qkv + (size_t)b * NN_TOK * 1536 + 1024 + head * 64;
    float* vrow_base = vimg + ((size_t)(b * CC + head * 64)) * PIX;
    const int nstart = j * KV_CHUNK;
    const int nend = min(nstart + KV_CHUNK, NN_TOK);

    for (int n0 = nstart; n0 < nend; n0 += 32) {
        #pragma unroll
        for (int i = 0; i < 2; i++) {
            int idx = t + i * 256;
            int nn = idx >> 4;
            int c4 = (idx & 15) * 4;
            int n = n0 + nn;
            float4 kk = make_float4(0.f, 0.f, 0.f, 0.f);
            float4 vv = make_float4(0.f, 0.f, 0.f, 0.f);
            if (n < nend) {
                kk = *(const float4*)&kbase[(size_t)n * 1536 + c4];
                vv = *(const float4*)&vbase[(size_t)n * 1536 + c4];
                kk.x = __expf(kk.x); kk.y = __expf(kk.y);
                kk.z = __expf(kk.z); kk.w = __expf(kk.w);
            }
            Ks[nn][c4 + 0] = kk.x; Ks[nn][c4 + 1] = kk.y;
            Ks[nn][c4 + 2] = kk.z; Ks[nn][c4 + 3] = kk.w;
            Vs[nn][c4 + 0] = vv.x; Vs[nn][c4 + 1] = vv.y;
            Vs[nn][c4 + 2] = vv.z; Vs[nn][c4 + 3] = vv.w;
        }
        __syncthreads();
        #pragma unroll
        for (int nn = 0; nn < 32; nn++) {
            float4 k4 = *(const float4*)&Ks[nn][rb];
            float4 v4 = *(const float4*)&Vs[nn][cb];
            float kr[4] = {k4.x, k4.y, k4.z, k4.w};
            float vr[4] = {v4.x, v4.y, v4.z, v4.w};
            #pragma unroll
            for (int i = 0; i < 4; i++)
                #pragma unroll
                for (int jj = 0; jj < 4; jj++)
                    acc[i][jj] = fmaf(kr[i], vr[jj], acc[i][jj]);
        }
        #pragma unroll
        for (int r = 0; r < 8; r++) mysum += Ks[sr + r][sc];
        {
            int n = n0 + lane;
            if (n >= 1 && n < nend) {
                #pragma unroll
                for (int pass = 0; pass < 8; pass++) {
                    int c = crow + pass * 8;
                    vrow_base[(size_t)c * PIX + (n - 1)] = Vs[lane][c];
                }
            }
        }
        __syncthreads();
    }

    part[t >> 6][sc] = mysum;
    __syncthreads();
    if (t < 64)
        sumpart[(bh * KV_CHUNKS + j) * 64 + t] =
            part[0][t] + part[1][t] + part[2][t] + part[3][t];

    float* dst = kvpart + ((size_t)(bh * KV_CHUNKS + j) * 64) * 64;
    #pragma unroll
    for (int i = 0; i < 4; i++)
        *(float4*)&dst[(rb + i) * 64 + cb] =
            make_float4(acc[i][0], acc[i][1], acc[i][2], acc[i][3]);
}

__global__ __launch_bounds__(256) void kv_reduce_kernel(const float* __restrict__ kvpart,
                                                        const float* __restrict__ sumpart,
                                                        float* __restrict__ kvout)
{
    int bh = blockIdx.x;
    int t = threadIdx.x;
    __shared__ float srcp[64];
    if (t < 64) {
        float s = 0.f;
        #pragma unroll
        for (int j = 0; j < KV_CHUNKS; j++)
            s += sumpart[(bh * KV_CHUNKS + j) * 64 + t];
        srcp[t] = 0.125f / s;
    }
    __syncthreads();
    const float* src = kvpart + (size_t)bh * KV_CHUNKS * 4096;
    #pragma unroll
    for (int i = 0; i < 16; i++) {
        int idx = t + i * 256;
        float v = 0.f;
        #pragma unroll
        for (int j = 0; j < KV_CHUNKS; j++)
            v += src[j * 4096 + idx];
        kvout[(size_t)bh * 4096 + idx] = v * srcp[idx >> 6];
    }
}

// ---------------- depthwise conv ----------------
__global__ __launch_bounds__(128) void dwconv_kernel(
    const float* __restrict__ vimg,
    const float* __restrict__ w3, const float* __restrict__ b3,
    const float* __restrict__ w5, const float* __restrict__ b5,
    const float* __restrict__ w7, const float* __restrict__ b7,
    float* __restrict__ convout)
{
    int bc = blockIdx.x;
    int c = bc & 511;
    __shared__ float timg[34 * 34];
    __shared__ float wsm[49];
    int t = threadIdx.x;
    const float* img = vimg + (size_t)bc * PIX;
    for (int i = t; i < 34 * 34; i += 128) {
        int y = i / 34 - 3, x = i % 34 - 3;
        timg[i] = (y >= 0 && y < HH && x >= 0 && x < WW) ? img[y * WW + x] : 0.f;
    }
    int ks; const float* wp; float bias;
    if (c < 128)      { ks = 3; wp = w3 + c * 9;          bias = b3[c]; }
    else if (c < 320) { ks = 5; wp = w5 + (c - 128) * 25; bias = b5[c - 128]; }
    else              { ks = 7; wp = w7 + (c - 320) * 49; bias = b7[c - 320]; }
    if (t < ks * ks) wsm[t] = wp[t];
    __syncthreads();
    int pad = ks >> 1;
    for (int p = t; p < PIX; p += 128) {
        int y = p / WW, x = p % WW;
        float s = bias;
        const int base = (y + 3 - pad) * 34 + (x + 3 - pad);
        for (int ky = 0; ky < ks; ky++)
            for (int kx = 0; kx < ks; kx++)
                s = fmaf(wsm[ky * ks + kx], timg[base + ky * 34 + kx], s);
        convout[(size_t)bc * PIX + p] = s;
    }
}

// ---------------- fused factor_att + crpe + fp16 split ----------------
__global__ __launch_bounds__(256) void factor_att_fused_kernel(
    const float* __restrict__ qkv, const float* __restrict__ kv,
    const float* __restrict__ conv,
    __half* __restrict__ ahi, __half* __restrict__ alo)
{
    int bh = blockIdx.y;
    int b = bh >> 3, head = bh & 7;
    int n0 = blockIdx.x * 64;
    __shared__ float QsT[64][68];
    __shared__ float KVs[64][64];
    __shared__ float CVs[64][65];
    int t = threadIdx.x;

    #pragma unroll
    for (int i = 0; i < 4; i++) {
        int idx = t + i * 256;
        int r = idx >> 4;
        int c4 = (idx & 15) * 4;
        *(float4*)&KVs[r][c4] = *(const float4*)&kv[((size_t)bh * 64 + r) * 64 + c4];
        int n = n0 + r;
        float4 q = make_float4(0.f, 0.f, 0.f, 0.f);
        if (n < NN_TOK)
            q = *(const float4*)&qkv[(size_t)(b * NN_TOK + n) * 1536 + head * 64 + c4];
        QsT[c4 + 0][r] = q.x;
        QsT[c4 + 1][r] = q.y;
        QsT[c4 + 2][r] = q.z;
        QsT[c4 + 3][r] = q.w;
    }
    #pragma unroll
    for (int i = 0; i < 4; i++) {
        int idx = t + i * 256;
        int c = idx >> 4;
        int j4 = (idx & 15) * 4;
        const float* cbase = conv + ((size_t)(b * CC + head * 64 + c)) * PIX;
        #pragma unroll
        for (int k = 0; k < 4; k++) {
            int n = n0 + j4 + k;
            CVs[c][j4 + k] = (n >= 1 && n < NN_TOK) ? cbase[n - 1] : 0.f;
        }
    }
    __syncthreads();

    float acc[4][4];
    #pragma unroll
    for (int i = 0; i < 4; i++)
        #pragma unroll
        for (int j = 0; j < 4; j++) acc[i][j] = 0.f;

    const int rb = (t >> 4) * 4;
    const int cb = (t & 15) * 4;
    #pragma unroll 4
    for (int c = 0; c < 64; c++) {
        float4 q4 = *(const float4*)&QsT[c][rb];
        float4 kv4 = *(const float4*)&KVs[c][cb];
        float qr[4] = {q4.x, q4.y, q4.z, q4.w};
        #pragma unroll
        for (int i = 0; i < 4; i++) {
            acc[i][0] = fmaf(qr[i], kv4.x, acc[i][0]);
            acc[i][1] = fmaf(qr[i], kv4.y, acc[i][1]);
            acc[i][2] = fmaf(qr[i], kv4.z, acc[i][2]);
            acc[i][3] = fmaf(qr[i], kv4.w, acc[i][3]);
        }
    }
    #pragma unroll
    for (int i = 0; i < 4; i++) {
        int n = n0 + rb + i;
        if (n < NN_TOK) {
            size_t base = (size_t)(b * NN_TOK + n) * CC + head * 64 + cb;
            float4 q4 = *(const float4*)&qkv[(size_t)(b * NN_TOK + n) * 1536 + head * 64 + cb];
            float qv[4] = {q4.x, q4.y, q4.z, q4.w};
            __half2 h2[2], l2[2];
            #pragma unroll
            for (int j = 0; j < 4; j += 2) {
                float f0 = acc[i][j]     + qv[j]     * CVs[cb + j][rb + i];
                float f1 = acc[i][j + 1] + qv[j + 1] * CVs[cb + j + 1][rb + i];
                __half h0 = __float2half_rn(f0), h1 = __float2half_rn(f1);
                h2[j >> 1] = __halves2half2(h0, h1);
                l2[j >> 1] = __halves2half2(__float2half_rn(f0 - __half2float(h0)),
                                            __float2half_rn(f1 - __half2float(h1)));
            }
            *(__half2*)(ahi + base)     = h2[0];
            *(__half2*)(ahi + base + 2) = h2[1];
            *(__half2*)(alo + base)     = l2[0];
            *(__half2*)(alo + base + 2) = l2[1];
        }
    }
}

// ---------------- launch ----------------
extern "C" void kernel_launch(void* const* d_in, const int* in_sizes, int n_in,
                              void* d_out, int out_size)
{
    const float* x      = (const float*)d_in[0];
    const float* qkv_w  = (const float*)d_in[1];
    const float* qkv_b  = (const float*)d_in[2];
    const float* proj_w = (const float*)d_in[3];
    const float* proj_b = (const float*)d_in[4];
    const float* w3     = (const float*)d_in[5];
    const float* b3     = (const float*)d_in[6];
    const float* w5     = (const float*)d_in[7];
    const float* b5     = (const float*)d_in[8];
    const float* w7     = (const float*)d_in[9];
    const float* b7     = (const float*)d_in[10];
    float* out = (float*)d_out;

    float *qkv, *kv, *kvpart, *sumpart, *vimg, *conv;
    __half *ahi, *alo, *wh, *ph;
    cudaGetSymbolAddress((void**)&qkv,     g_qkv);
    cudaGetSymbolAddress((void**)&kv,      g_kv);
    cudaGetSymbolAddress((void**)&kvpart,  g_kvpart);
    cudaGetSymbolAddress((void**)&sumpart, g_sumpart);
    cudaGetSymbolAddress((void**)&vimg,    g_vimg);
    cudaGetSymbolAddress((void**)&conv,    g_conv);
    cudaGetSymbolAddress((void**)&ahi,     g_ahi);
    cudaGetSymbolAddress((void**)&alo,     g_alo);
    cudaGetSymbolAddress((void**)&wh,      g_wh);
    cudaGetSymbolAddress((void**)&ph,      g_ph);

    cudaFuncSetAttribute(gemm_mma_kernel,
                         cudaFuncAttributeMaxDynamicSharedMemorySize, GEMM_SMEM);

    const int M = MTOT;
    const int mtiles = (M + Bb - 1) / Bb;   // 197

    // conversions
    {
        int n4 = M * KK / 4;
        split_kernel<<<(n4 + 255) / 256, 256>>>(x, ahi, alo, n4);
        n4 = 1536 * KK / 4;
        cvt_kernel<<<(n4 + 255) / 256, 256>>>(qkv_w, wh, n4);
        n4 = 512 * KK / 4;
        cvt_kernel<<<(n4 + 255) / 256, 256>>>(proj_w, ph, n4);
    }

    // GEMM1: qkv = x @ qkv_w^T + qkv_b    [M, 1536]
    gemm_mma_kernel<<<dim3(1536 / BN, mtiles), 256, GEMM_SMEM>>>(
        ahi, alo, wh, qkv_b, qkv, M, 1536);

    // attention middle (kv partials also emit transposed v)
    kv_partial_kernel<<<dim3(256, KV_CHUNKS), 256>>>(qkv, kvpart, sumpart, vimg);
    kv_reduce_kernel<<<256, 256>>>(kvpart, sumpart, kv);
    dwconv_kernel<<<BB * CC, 128>>>(vimg, w3, b3, w5, b5, w7, b7, conv);
    factor_att_fused_kernel<<<dim3((NN_TOK + 63) / 64, 256), 256>>>(
        qkv, kv, conv, ahi, alo);

    // GEMM2: out = att @ proj_w^T + proj_b   [M, 512]
    gemm_mma_kernel<<<dim3(512 / BN, mtiles), 256, GEMM_SMEM>>>(
        ahi, alo, ph, proj_b, out, M, 512);
}

// round 16
// speedup vs baseline: 1.6850x; 1.0494x over previous
#include <cuda_runtime.h>
#include <cuda_fp16.h>
#include <math.h>
#include <stdint.h>

// Problem constants
#define BB 32
#define NN_TOK 785
#define CC 512
#define NH 8
#define CH 64
#define HH 28
#define WW 28
#define PIX 784
#define MTOT (BB*NN_TOK)   // 25120
#define KK 512             // GEMM K
#define KV_CHUNKS 8
#define KV_CHUNK 99

// ---------------- scratch ----------------
__device__ float g_qkv[(size_t)MTOT * 1536];
__device__ float g_kv[BB * NH * CH * CH];
__device__ float g_kvpart[(size_t)BB * NH * KV_CHUNKS * CH * CH];
__device__ float g_sumpart[BB * NH * KV_CHUNKS * CH];
__device__ float g_vimg[(size_t)BB * CC * PIX];
__device__ float g_conv[(size_t)BB * CC * PIX];
// fp16 buffers
__device__ __half g_ahi[(size_t)MTOT * KK];
__device__ __half g_alo[(size_t)MTOT * KK];
__device__ __half g_wh[1536 * KK];
__device__ __half g_ph[512 * KK];

// ---------------- helpers ----------------
__device__ __forceinline__ uint32_t smem_u32(const void* p) {
    uint32_t a;
    asm("{ .reg .u64 t; cvta.to.shared.u64 t, %1; cvt.u32.u64 %0, t; }" : "=r"(a) : "l"(p));
    return a;
}

template<int N> __device__ __forceinline__ void cp_wait() {
    asm volatile("cp.async.wait_group %0;" :: "n"(N) : "memory");
}
__device__ __forceinline__ void cp_commit() {
    asm volatile("cp.async.commit_group;" ::: "memory");
}
__device__ __forceinline__ void cp_async16(uint32_t dst, const void* src, uint32_t src_bytes) {
    asm volatile("cp.async.cg.shared.global [%0], [%1], 16, %2;"
                 :: "r"(dst), "l"(src), "r"(src_bytes));
}

__device__ __forceinline__ void mma_f16(float* d, const uint32_t* a, const uint32_t* b) {
    asm volatile("mma.sync.aligned.m16n8k16.row.col.f32.f16.f16.f32 "
        "{%0,%1,%2,%3}, {%4,%5,%6,%7}, {%8,%9}, {%0,%1,%2,%3};"
        : "+f"(d[0]), "+f"(d[1]), "+f"(d[2]), "+f"(d[3])
        : "r"(a[0]), "r"(a[1]), "r"(a[2]), "r"(a[3]), "r"(b[0]), "r"(b[1]));
}

__device__ __forceinline__ void ldmatrix_x4(uint32_t* r, uint32_t addr) {
    asm volatile("ldmatrix.sync.aligned.m8n8.x4.shared.b16 {%0,%1,%2,%3}, [%4];"
        : "=r"(r[0]), "=r"(r[1]), "=r"(r[2]), "=r"(r[3]) : "r"(addr));
}

// ---------------- fp32 -> (hi, lo) fp16 split ----------------
__global__ void split_kernel(const float* __restrict__ in,
                             __half* __restrict__ hi,
                             __half* __restrict__ lo, int n4)
{
    int i = blockIdx.x * blockDim.x + threadIdx.x;
    if (i >= n4) return;
    float4 v = ((const float4*)in)[i];
    __half hx = __float2half_rn(v.x), hy = __float2half_rn(v.y);
    __half hz = __float2half_rn(v.z), hw = __float2half_rn(v.w);
    __half lx = __float2half_rn(v.x - __half2float(hx));
    __half ly = __float2half_rn(v.y - __half2float(hy));
    __half lz = __float2half_rn(v.z - __half2float(hz));
    __half lw = __float2half_rn(v.w - __half2float(hw));
    ((__half2*)hi)[i * 2 + 0] = __halves2half2(hx, hy);
    ((__half2*)hi)[i * 2 + 1] = __halves2half2(hz, hw);
    ((__half2*)lo)[i * 2 + 0] = __halves2half2(lx, ly);
    ((__half2*)lo)[i * 2 + 1] = __halves2half2(lz, lw);
}

// ---------------- fp32 -> fp16 convert (weights) ----------------
__global__ void cvt_kernel(const float* __restrict__ in, __half* __restrict__ out, int n4)
{
    int i = blockIdx.x * blockDim.x + threadIdx.x;
    if (i >= n4) return;
    float4 v = ((const float4*)in)[i];
    ((__half2*)out)[i * 2 + 0] = __floats2half2_rn(v.x, v.y);
    ((__half2*)out)[i * 2 + 1] = __floats2half2_rn(v.z, v.w);
}

// ---------------- mma.sync GEMM (templated on lo-pass) ----------------
// Warp tile 32x64 (mi=2, ni=8). USE_LO: A = Ahi + Alo (2-pass); else plain fp16 A.
#define Bb 128
#define BN 128
#define BK 32
#define ASTR 40
#define ARR_ELEMS (128 * ASTR)
#define STAGE_ELEMS (3 * ARR_ELEMS)
#define NSTAGE 3
#define GEMM_SMEM (NSTAGE * STAGE_ELEMS * 2)  // 92160 bytes
#define NCHUNK (KK / BK)

template<bool USE_LO>
__global__ __launch_bounds__(256, 2) void gemm_mma_kernel(
    const __half* __restrict__ Ahi, const __half* __restrict__ Alo,
    const __half* __restrict__ W,
    const float* __restrict__ bias, float* __restrict__ C,
    int M, int Nw)
{
    extern __shared__ __half sm[];
    const uint32_t smem_base = smem_u32(sm);
    const int t = threadIdx.x;
    const int lane = t & 31;
    const int wid = t >> 5;
    const int bm = blockIdx.y * Bb;
    const int bn = blockIdx.x * BN;
    const int m_base = (wid & 3) * 32;
    const int n_base = (wid >> 2) * 64;

    const int la = lane & 7;
    const int aRowOff = m_base + la + ((lane >> 3) & 1) * 8;
    const int aColOff = (lane >> 4) * 8;
    const int bRowOff = n_base + la + ((lane >> 4) & 1) * 8;
    const int bColOff = ((lane >> 3) & 1) * 8;

    float acc[2][8][4];
    #pragma unroll
    for (int mi = 0; mi < 2; mi++)
        #pragma unroll
        for (int ni = 0; ni < 8; ni++)
            #pragma unroll
            for (int j = 0; j < 4; j++) acc[mi][ni][j] = 0.f;

    auto load_stage = [&](int stage, int k0) {
        if (USE_LO) {
            #pragma unroll
            for (int i = 0; i < 6; i++) {
                int idx = t + i * 256;
                int arr = idx >> 9;          // 0:Ahi 1:Alo 2:B
                int sub = idx & 511;
                int row = sub >> 2;
                int seg = sub & 3;
                const __half* src;
                uint32_t nbytes = 16;
                if (arr < 2) {
                    int gr = bm + row;
                    if (gr >= M) { gr = 0; nbytes = 0; }
                    src = (arr == 0 ? Ahi : Alo) + (size_t)gr * KK + k0 + seg * 8;
                } else {
                    src = W + (size_t)(bn + row) * KK + k0 + seg * 8;
                }
                uint32_t dst = smem_base +
                    (uint32_t)(stage * STAGE_ELEMS + arr * ARR_ELEMS + row * ASTR + seg * 8) * 2;
                cp_async16(dst, src, nbytes);
            }
        } else {
            #pragma unroll
            for (int i = 0; i < 4; i++) {
                int idx = t + i * 256;
                int isB = idx >> 9;          // 0:Ahi 1:B
                int sub = idx & 511;
                int row = sub >> 2;
                int seg = sub & 3;
                const __half* src;
                uint32_t nbytes = 16;
                int arr;
                if (!isB) {
                    int gr = bm + row;
                    if (gr >= M) { gr = 0; nbytes = 0; }
                    src = Ahi + (size_t)gr * KK + k0 + seg * 8;
                    arr = 0;
                } else {
                    src = W + (size_t)(bn + row) * KK + k0 + seg * 8;
                    arr = 2;
                }
                uint32_t dst = smem_base +
                    (uint32_t)(stage * STAGE_ELEMS + arr * ARR_ELEMS + row * ASTR + seg * 8) * 2;
                cp_async16(dst, src, nbytes);
            }
        }
        cp_commit();
    };

    auto compute_stage = [&](int stage) {
        const uint32_t sbase = smem_base + (uint32_t)(stage * STAGE_ELEMS) * 2;
        const uint32_t aHiB = sbase;
        const uint32_t aLoB = sbase + (uint32_t)ARR_ELEMS * 2;
        const uint32_t bB   = sbase + (uint32_t)(2 * ARR_ELEMS) * 2;
        #pragma unroll
        for (int kk = 0; kk < BK; kk += 16) {
            uint32_t bf[8][2], ah[2][4], al[2][4];
            const uint32_t aOff = (uint32_t)(aRowOff * ASTR + aColOff + kk) * 2;
            const uint32_t bOff = (uint32_t)(bRowOff * ASTR + bColOff + kk) * 2;
            #pragma unroll
            for (int pr = 0; pr < 4; pr++) {
                uint32_t r[4];
                ldmatrix_x4(r, bB + bOff + (uint32_t)(pr * 16 * ASTR) * 2);
                bf[pr * 2][0] = r[0]; bf[pr * 2][1] = r[1];
                bf[pr * 2 + 1][0] = r[2]; bf[pr * 2 + 1][1] = r[3];
            }
            #pragma unroll
            for (int mi = 0; mi < 2; mi++)
                ldmatrix_x4(ah[mi], aHiB + aOff + (uint32_t)(mi * 16 * ASTR) * 2);
            if (USE_LO) {
                #pragma unroll
                for (int mi = 0; mi < 2; mi++)
                    ldmatrix_x4(al[mi], aLoB + aOff + (uint32_t)(mi * 16 * ASTR) * 2);
            }
            #pragma unroll
            for (int mi = 0; mi < 2; mi++)
                #pragma unroll
                for (int ni = 0; ni < 8; ni++)
                    mma_f16(acc[mi][ni], ah[mi], bf[ni]);
            if (USE_LO) {
                #pragma unroll
                for (int mi = 0; mi < 2; mi++)
                    #pragma unroll
                    for (int ni = 0; ni < 8; ni++)
                        mma_f16(acc[mi][ni], al[mi], bf[ni]);
            }
        }
    };

    load_stage(0, 0);
    load_stage(1, BK);
    #pragma unroll 1
    for (int c = 0; c < NCHUNK; c++) {
        if (c < NCHUNK - 1) cp_wait<1>(); else cp_wait<0>();
        __syncthreads();
        compute_stage(c % 3);
        if (c + 2 < NCHUNK) load_stage((c + 2) % 3, (c + 2) * BK);
    }

    #pragma unroll
    for (int mi = 0; mi < 2; mi++) {
        #pragma unroll
        for (int ni = 0; ni < 8; ni++) {
            int row = bm + m_base + mi * 16 + (lane >> 2);
            int col = bn + n_base + ni * 8 + (lane & 3) * 2;
            float2 bv = *(const float2*)(bias + col);
            if (row < M) {
                float2 o = make_float2(acc[mi][ni][0] + bv.x, acc[mi][ni][1] + bv.y);
                *(float2*)(C + (size_t)row * Nw + col) = o;
            }
            if (row + 8 < M) {
                float2 o = make_float2(acc[mi][ni][2] + bv.x, acc[mi][ni][3] + bv.y);
                *(float2*)(C + (size_t)(row + 8) * Nw + col) = o;
            }
        }
    }
}

// ---------------- fused softmax+kv partials + v-transpose writeout ----------------
__global__ __launch_bounds__(256) void kv_partial_kernel(const float* __restrict__ qkv,
                                                         float* __restrict__ kvpart,
                                                         float* __restrict__ sumpart,
                                                         float* __restrict__ vimg)
{
    int bh = blockIdx.x;
    int j = blockIdx.y;
    int b = bh >> 3, head = bh & 7;
    __shared__ float Ks[32][64];
    __shared__ float Vs[32][68];
    __shared__ float part[4][64];
    int t = threadIdx.x;

    float acc[4][4];
    #pragma unroll
    for (int i = 0; i < 4; i++)
        #pragma unroll
        for (int jj = 0; jj < 4; jj++) acc[i][jj] = 0.f;
    float mysum = 0.f;

    const int rb = (t >> 4) * 4;
    const int cb = (t & 15) * 4;
    const int sr = (t >> 6) * 8;
    const int sc = t & 63;
    const int lane = t & 31;
    const int crow = t >> 5;
    const float* kbase = qkv + (size_t)b * NN_TOK * 1536 + 512 + head * 64;
    const float* vbase = qkv + (size_t)b * NN_TOK * 1536 + 1024 + head * 64;
    float* vrow_base = vimg + ((size_t)(b * CC + head * 64)) * PIX;
    const int nstart = j * KV_CHUNK;
    const int nend = min(nstart + KV_CHUNK, NN_TOK);

    for (int n0 = nstart; n0 < nend; n0 += 32) {
        #pragma unroll
        for (int i = 0; i < 2; i++) {
            int idx = t + i * 256;
            int nn = idx >> 4;
            int c4 = (idx & 15) * 4;
            int n = n0 + nn;
            float4 kk = make_float4(0.f, 0.f, 0.f, 0.f);
            float4 vv = make_float4(0.f, 0.f, 0.f, 0.f);
            if (n < nend) {
                kk = *(const float4*)&kbase[(size_t)n * 1536 + c4];
                vv = *(const float4*)&vbase[(size_t)n * 1536 + c4];
                kk.x = __expf(kk.x); kk.y = __expf(kk.y);
                kk.z = __expf(kk.z); kk.w = __expf(kk.w);
            }
            Ks[nn][c4 + 0] = kk.x; Ks[nn][c4 + 1] = kk.y;
            Ks[nn][c4 + 2] = kk.z; Ks[nn][c4 + 3] = kk.w;
            Vs[nn][c4 + 0] = vv.x; Vs[nn][c4 + 1] = vv.y;
            Vs[nn][c4 + 2] = vv.z; Vs[nn][c4 + 3] = vv.w;
        }
        __syncthreads();
        #pragma unroll
        for (int nn = 0; nn < 32; nn++) {
            float4 k4 = *(const float4*)&Ks[nn][rb];
            float4 v4 = *(const float4*)&Vs[nn][cb];
            float kr[4] = {k4.x, k4.y, k4.z, k4.w};
            float vr[4] = {v4.x, v4.y, v4.z, v4.w};
            #pragma unroll
            for (int i = 0; i < 4; i++)
                #pragma unroll
                for (int jj = 0; jj < 4; jj++)
                    acc[i][jj] = fmaf(kr[i], vr[jj], acc[i][jj]);
        }
        #pragma unroll
        for (int r = 0; r < 8; r++) mysum += Ks[sr + r][sc];
        {
            int n = n0 + lane;
            if (n >= 1 && n < nend) {
                #pragma unroll
                for (int pass = 0; pass < 8; pass++) {
                    int c = crow + pass * 8;
                    vrow_base[(size_t)c * PIX + (n - 1)] = Vs[lane][c];
                }
            }
        }
        __syncthreads();
    }

    part[t >> 6][sc] = mysum;
    __syncthreads();
    if (t < 64)
        sumpart[(bh * KV_CHUNKS + j) * 64 + t] =
            part[0][t] + part[1][t] + part[2][t] + part[3][t];

    float* dst = kvpart + ((size_t)(bh * KV_CHUNKS + j) * 64) * 64;
    #pragma unroll
    for (int i = 0; i < 4; i++)
        *(float4*)&dst[(rb + i) * 64 + cb] =
            make_float4(acc[i][0], acc[i][1], acc[i][2], acc[i][3]);
}

__global__ __launch_bounds__(256) void kv_reduce_kernel(const float* __restrict__ kvpart,
                                                        const float* __restrict__ sumpart,
                                                        float* __restrict__ kvout)
{
    int bh = blockIdx.x;
    int t = threadIdx.x;
    __shared__ float srcp[64];
    if (t < 64) {
        float s = 0.f;
        #pragma unroll
        for (int j = 0; j < KV_CHUNKS; j++)
            s += sumpart[(bh * KV_CHUNKS + j) * 64 + t];
        srcp[t] = 0.125f / s;
    }
    __syncthreads();
    const float* src = kvpart + (size_t)bh * KV_CHUNKS * 4096;
    #pragma unroll
    for (int i = 0; i < 16; i++) {
        int idx = t + i * 256;
        float v = 0.f;
        #pragma unroll
        for (int j = 0; j < KV_CHUNKS; j++)
            v += src[j * 4096 + idx];
        kvout[(size_t)bh * 4096 + idx] = v * srcp[idx >> 6];
    }
}

// ---------------- depthwise conv ----------------
__global__ __launch_bounds__(128) void dwconv_kernel(
    const float* __restrict__ vimg,
    const float* __restrict__ w3, const float* __restrict__ b3,
    const float* __restrict__ w5, const float* __restrict__ b5,
    const float* __restrict__ w7, const float* __restrict__ b7,
    float* __restrict__ convout)
{
    int bc = blockIdx.x;
    int c = bc & 511;
    __shared__ float timg[34 * 34];
    __shared__ float wsm[49];
    int t = threadIdx.x;
    const float* img = vimg + (size_t)bc * PIX;
    for (int i = t; i < 34 * 34; i += 128) {
        int y = i / 34 - 3, x = i % 34 - 3;
        timg[i] = (y >= 0 && y < HH && x >= 0 && x < WW) ? img[y * WW + x] : 0.f;
    }
    int ks; const float* wp; float bias;
    if (c < 128)      { ks = 3; wp = w3 + c * 9;          bias = b3[c]; }
    else if (c < 320) { ks = 5; wp = w5 + (c - 128) * 25; bias = b5[c - 128]; }
    else              { ks = 7; wp = w7 + (c - 320) * 49; bias = b7[c - 320]; }
    if (t < ks * ks) wsm[t] = wp[t];
    __syncthreads();
    int pad = ks >> 1;
    for (int p = t; p < PIX; p += 128) {
        int y = p / WW, x = p % WW;
        float s = bias;
        const int base = (y + 3 - pad) * 34 + (x + 3 - pad);
        for (int ky = 0; ky < ks; ky++)
            for (int kx = 0; kx < ks; kx++)
                s = fmaf(wsm[ky * ks + kx], timg[base + ky * 34 + kx], s);
        convout[(size_t)bc * PIX + p] = s;
    }
}

// ---------------- fused factor_att + crpe + fp16 convert (hi only) ----------------
__global__ __launch_bounds__(256) void factor_att_fused_kernel(
    const float* __restrict__ qkv, const float* __restrict__ kv,
    const float* __restrict__ conv,
    __half* __restrict__ ahi)
{
    int bh = blockIdx.y;
    int b = bh >> 3, head = bh & 7;
    int n0 = blockIdx.x * 64;
    __shared__ float QsT[64][68];
    __shared__ float KVs[64][64];
    __shared__ float CVs[64][65];
    int t = threadIdx.x;

    #pragma unroll
    for (int i = 0; i < 4; i++) {
        int idx = t + i * 256;
        int r = idx >> 4;
        int c4 = (idx & 15) * 4;
        *(float4*)&KVs[r][c4] = *(const float4*)&kv[((size_t)bh * 64 + r) * 64 + c4];
        int n = n0 + r;
        float4 q = make_float4(0.f, 0.f, 0.f, 0.f);
        if (n < NN_TOK)
            q = *(const float4*)&qkv[(size_t)(b * NN_TOK + n) * 1536 + head * 64 + c4];
        QsT[c4 + 0][r] = q.x;
        QsT[c4 + 1][r] = q.y;
        QsT[c4 + 2][r] = q.z;
        QsT[c4 + 3][r] = q.w;
    }
    #pragma unroll
    for (int i = 0; i < 4; i++) {
        int idx = t + i * 256;
        int c = idx >> 4;
        int j4 = (idx & 15) * 4;
        const float* cbase = conv + ((size_t)(b * CC + head * 64 + c)) * PIX;
        #pragma unroll
        for (int k = 0; k < 4; k++) {
            int n = n0 + j4 + k;
            CVs[c][j4 + k] = (n >= 1 && n < NN_TOK) ? cbase[n - 1] : 0.f;
        }
    }
    __syncthreads();

    float acc[4][4];
    #pragma unroll
    for (int i = 0; i < 4; i++)
        #pragma unroll
        for (int j = 0; j < 4; j++) acc[i][j] = 0.f;

    const int rb = (t >> 4) * 4;
    const int cb = (t & 15) * 4;
    #pragma unroll 4
    for (int c = 0; c < 64; c++) {
        float4 q4 = *(const float4*)&QsT[c][rb];
        float4 kv4 = *(const float4*)&KVs[c][cb];
        float qr[4] = {q4.x, q4.y, q4.z, q4.w};
        #pragma unroll
        for (int i = 0; i < 4; i++) {
            acc[i][0] = fmaf(qr[i], kv4.x, acc[i][0]);
            acc[i][1] = fmaf(qr[i], kv4.y, acc[i][1]);
            acc[i][2] = fmaf(qr[i], kv4.z, acc[i][2]);
            acc[i][3] = fmaf(qr[i], kv4.w, acc[i][3]);
        }
    }
    #pragma unroll
    for (int i = 0; i < 4; i++) {
        int n = n0 + rb + i;
        if (n < NN_TOK) {
            size_t base = (size_t)(b * NN_TOK + n) * CC + head * 64 + cb;
            float4 q4 = *(const float4*)&qkv[(size_t)(b * NN_TOK + n) * 1536 + head * 64 + cb];
            float qv[4] = {q4.x, q4.y, q4.z, q4.w};
            float f0 = acc[i][0] + qv[0] * CVs[cb + 0][rb + i];
            float f1 = acc[i][1] + qv[1] * CVs[cb + 1][rb + i];
            float f2 = acc[i][2] + qv[2] * CVs[cb + 2][rb + i];
            float f3 = acc[i][3] + qv[3] * CVs[cb + 3][rb + i];
            __half2 h0 = __floats2half2_rn(f0, f1);
            __half2 h1 = __floats2half2_rn(f2, f3);
            *(__half2*)(ahi + base)     = h0;
            *(__half2*)(ahi + base + 2) = h1;
        }
    }
}

// ---------------- launch ----------------
extern "C" void kernel_launch(void* const* d_in, const int* in_sizes, int n_in,
                              void* d_out, int out_size)
{
    const float* x      = (const float*)d_in[0];
    const float* qkv_w  = (const float*)d_in[1];
    const float* qkv_b  = (const float*)d_in[2];
    const float* proj_w = (const float*)d_in[3];
    const float* proj_b = (const float*)d_in[4];
    const float* w3     = (const float*)d_in[5];
    const float* b3     = (const float*)d_in[6];
    const float* w5     = (const float*)d_in[7];
    const float* b5     = (const float*)d_in[8];
    const float* w7     = (const float*)d_in[9];
    const float* b7     = (const float*)d_in[10];
    float* out = (float*)d_out;

    float *qkv, *kv, *kvpart, *sumpart, *vimg, *conv;
    __half *ahi, *alo, *wh, *ph;
    cudaGetSymbolAddress((void**)&qkv,     g_qkv);
    cudaGetSymbolAddress((void**)&kv,      g_kv);
    cudaGetSymbolAddress((void**)&kvpart,  g_kvpart);
    cudaGetSymbolAddress((void**)&sumpart, g_sumpart);
    cudaGetSymbolAddress((void**)&vimg,    g_vimg);
    cudaGetSymbolAddress((void**)&conv,    g_conv);
    cudaGetSymbolAddress((void**)&ahi,     g_ahi);
    cudaGetSymbolAddress((void**)&alo,     g_alo);
    cudaGetSymbolAddress((void**)&wh,      g_wh);
    cudaGetSymbolAddress((void**)&ph,      g_ph);

    cudaFuncSetAttribute(gemm_mma_kernel<true>,
                         cudaFuncAttributeMaxDynamicSharedMemorySize, GEMM_SMEM);
    cudaFuncSetAttribute(gemm_mma_kernel<false>,
                         cudaFuncAttributeMaxDynamicSharedMemorySize, GEMM_SMEM);

    const int M = MTOT;
    const int mtiles = (M + Bb - 1) / Bb;   // 197

    // conversions
    {
        int n4 = M * KK / 4;
        split_kernel<<<(n4 + 255) / 256, 256>>>(x, ahi, alo, n4);
        n4 = 1536 * KK / 4;
        cvt_kernel<<<(n4 + 255) / 256, 256>>>(qkv_w, wh, n4);
        n4 = 512 * KK / 4;
        cvt_kernel<<<(n4 + 255) / 256, 256>>>(proj_w, ph, n4);
    }

    // GEMM1 (full hi+lo emulation): qkv = x @ qkv_w^T + qkv_b
    gemm_mma_kernel<true><<<dim3(1536 / BN, mtiles), 256, GEMM_SMEM>>>(
        ahi, alo, wh, qkv_b, qkv, M, 1536);

    // attention middle
    kv_partial_kernel<<<dim3(256, KV_CHUNKS), 256>>>(qkv, kvpart, sumpart, vimg);
    kv_reduce_kernel<<<256, 256>>>(kvpart, sumpart, kv);
    dwconv_kernel<<<BB * CC, 128>>>(vimg, w3, b3, w5, b5, w7, b7, conv);
    factor_att_fused_kernel<<<dim3((NN_TOK + 63) / 64, 256), 256>>>(
        qkv, kv, conv, ahi);

    // GEMM2 (plain fp16 A): out = att @ proj_w^T + proj_b
    gemm_mma_kernel<false><<<dim3(512 / BN, mtiles), 256, GEMM_SMEM>>>(
        ahi, ahi, ph, proj_b, out, M, 512);
}

// round 17
// speedup vs baseline: 1.9199x; 1.1394x over previous
#include <cuda_runtime.h>
#include <cuda_fp16.h>
#include <math.h>
#include <stdint.h>

// Problem constants
#define BB 32
#define NN_TOK 785
#define CC 512
#define NH 8
#define CH 64
#define HH 28
#define WW 28
#define PIX 784
#define MTOT (BB*NN_TOK)   // 25120
#define KK 512             // GEMM K
#define KV_CHUNKS 8
#define KV_CHUNK 99

// ---------------- scratch ----------------
__device__ float g_qkv[(size_t)MTOT * 1536];
__device__ float g_kv[BB * NH * CH * CH];
__device__ float g_kvpart[(size_t)BB * NH * KV_CHUNKS * CH * CH];
__device__ float g_sumpart[BB * NH * KV_CHUNKS * CH];
__device__ float g_vimg[(size_t)BB * CC * PIX];
__device__ float g_conv[(size_t)BB * CC * PIX];
// fp16 buffers
__device__ __half g_ah[(size_t)MTOT * KK];
__device__ __half g_wh[1536 * KK];
__device__ __half g_ph[512 * KK];

// ---------------- helpers ----------------
__device__ __forceinline__ uint32_t smem_u32(const void* p) {
    uint32_t a;
    asm("{ .reg .u64 t; cvta.to.shared.u64 t, %1; cvt.u32.u64 %0, t; }" : "=r"(a) : "l"(p));
    return a;
}

template<int N> __device__ __forceinline__ void cp_wait() {
    asm volatile("cp.async.wait_group %0;" :: "n"(N) : "memory");
}
__device__ __forceinline__ void cp_commit() {
    asm volatile("cp.async.commit_group;" ::: "memory");
}
__device__ __forceinline__ void cp_async16(uint32_t dst, const void* src, uint32_t src_bytes) {
    asm volatile("cp.async.cg.shared.global [%0], [%1], 16, %2;"
                 :: "r"(dst), "l"(src), "r"(src_bytes));
}

__device__ __forceinline__ void mma_f16(float* d, const uint32_t* a, const uint32_t* b) {
    asm volatile("mma.sync.aligned.m16n8k16.row.col.f32.f16.f16.f32 "
        "{%0,%1,%2,%3}, {%4,%5,%6,%7}, {%8,%9}, {%0,%1,%2,%3};"
        : "+f"(d[0]), "+f"(d[1]), "+f"(d[2]), "+f"(d[3])
        : "r"(a[0]), "r"(a[1]), "r"(a[2]), "r"(a[3]), "r"(b[0]), "r"(b[1]));
}

__device__ __forceinline__ void ldmatrix_x4(uint32_t* r, uint32_t addr) {
    asm volatile("ldmatrix.sync.aligned.m8n8.x4.shared.b16 {%0,%1,%2,%3}, [%4];"
        : "=r"(r[0]), "=r"(r[1]), "=r"(r[2]), "=r"(r[3]) : "r"(addr));
}

// ---------------- fp32 -> fp16 convert ----------------
__global__ void cvt_kernel(const float* __restrict__ in, __half* __restrict__ out, int n4)
{
    int i = blockIdx.x * blockDim.x + threadIdx.x;
    if (i >= n4) return;
    float4 v = ((const float4*)in)[i];
    ((__half2*)out)[i * 2 + 0] = __floats2half2_rn(v.x, v.y);
    ((__half2*)out)[i * 2 + 1] = __floats2half2_rn(v.z, v.w);
}

// ---------------- mma.sync GEMM: C[M,Nw] = A[f16] @ W[f16]^T + bias ----------------
// Warp tile 32x64 (mi=2, ni=8).
#define Bb 128
#define BN 128
#define BK 32
#define ASTR 40
#define ARR_ELEMS (128 * ASTR)
#define STAGE_ELEMS (2 * ARR_ELEMS)      // A, B
#define NSTAGE 3
#define GEMM_SMEM (NSTAGE * STAGE_ELEMS * 2)  // 61440 bytes
#define NCHUNK (KK / BK)

__global__ __launch_bounds__(256, 2) void gemm_mma_kernel(
    const __half* __restrict__ A,
    const __half* __restrict__ W,
    const float* __restrict__ bias, float* __restrict__ C,
    int M, int Nw)
{
    extern __shared__ __half sm[];
    const uint32_t smem_base = smem_u32(sm);
    const int t = threadIdx.x;
    const int lane = t & 31;
    const int wid = t >> 5;
    const int bm = blockIdx.y * Bb;
    const int bn = blockIdx.x * BN;
    const int m_base = (wid & 3) * 32;
    const int n_base = (wid >> 2) * 64;

    const int la = lane & 7;
    const int aRowOff = m_base + la + ((lane >> 3) & 1) * 8;
    const int aColOff = (lane >> 4) * 8;
    const int bRowOff = n_base + la + ((lane >> 4) & 1) * 8;
    const int bColOff = ((lane >> 3) & 1) * 8;

    float acc[2][8][4];
    #pragma unroll
    for (int mi = 0; mi < 2; mi++)
        #pragma unroll
        for (int ni = 0; ni < 8; ni++)
            #pragma unroll
            for (int j = 0; j < 4; j++) acc[mi][ni][j] = 0.f;

    auto load_stage = [&](int stage, int k0) {
        #pragma unroll
        for (int i = 0; i < 4; i++) {
            int idx = t + i * 256;
            int isB = idx >> 9;          // 0:A 1:B
            int sub = idx & 511;
            int row = sub >> 2;
            int seg = sub & 3;
            const __half* src;
            uint32_t nbytes = 16;
            if (!isB) {
                int gr = bm + row;
                if (gr >= M) { gr = 0; nbytes = 0; }
                src = A + (size_t)gr * KK + k0 + seg * 8;
            } else {
                src = W + (size_t)(bn + row) * KK + k0 + seg * 8;
            }
            uint32_t dst = smem_base +
                (uint32_t)(stage * STAGE_ELEMS + isB * ARR_ELEMS + row * ASTR + seg * 8) * 2;
            cp_async16(dst, src, nbytes);
        }
        cp_commit();
    };

    auto compute_stage = [&](int stage) {
        const uint32_t sbase = smem_base + (uint32_t)(stage * STAGE_ELEMS) * 2;
        const uint32_t aB = sbase;
        const uint32_t bB = sbase + (uint32_t)ARR_ELEMS * 2;
        #pragma unroll
        for (int kk = 0; kk < BK; kk += 16) {
            uint32_t bf[8][2], af[2][4];
            const uint32_t aOff = (uint32_t)(aRowOff * ASTR + aColOff + kk) * 2;
            const uint32_t bOff = (uint32_t)(bRowOff * ASTR + bColOff + kk) * 2;
            #pragma unroll
            for (int pr = 0; pr < 4; pr++) {
                uint32_t r[4];
                ldmatrix_x4(r, bB + bOff + (uint32_t)(pr * 16 * ASTR) * 2);
                bf[pr * 2][0] = r[0]; bf[pr * 2][1] = r[1];
                bf[pr * 2 + 1][0] = r[2]; bf[pr * 2 + 1][1] = r[3];
            }
            #pragma unroll
            for (int mi = 0; mi < 2; mi++)
                ldmatrix_x4(af[mi], aB + aOff + (uint32_t)(mi * 16 * ASTR) * 2);
            #pragma unroll
            for (int mi = 0; mi < 2; mi++)
                #pragma unroll
                for (int ni = 0; ni < 8; ni++)
                    mma_f16(acc[mi][ni], af[mi], bf[ni]);
        }
    };

    load_stage(0, 0);
    load_stage(1, BK);
    #pragma unroll 1
    for (int c = 0; c < NCHUNK; c++) {
        if (c < NCHUNK - 1) cp_wait<1>(); else cp_wait<0>();
        __syncthreads();
        compute_stage(c % 3);
        if (c + 2 < NCHUNK) load_stage((c + 2) % 3, (c + 2) * BK);
    }

    #pragma unroll
    for (int mi = 0; mi < 2; mi++) {
        #pragma unroll
        for (int ni = 0; ni < 8; ni++) {
            int row = bm + m_base + mi * 16 + (lane >> 2);
            int col = bn + n_base + ni * 8 + (lane & 3) * 2;
            float2 bv = *(const float2*)(bias + col);
            if (row < M) {
                float2 o = make_float2(acc[mi][ni][0] + bv.x, acc[mi][ni][1] + bv.y);
                *(float2*)(C + (size_t)row * Nw + col) = o;
            }
            if (row + 8 < M) {
                float2 o = make_float2(acc[mi][ni][2] + bv.x, acc[mi][ni][3] + bv.y);
                *(float2*)(C + (size_t)(row + 8) * Nw + col) = o;
            }
        }
    }
}

// ---------------- fused softmax+kv partials + v-transpose writeout ----------------
__global__ __launch_bounds__(256) void kv_partial_kernel(const float* __restrict__ qkv,
                                                         float* __restrict__ kvpart,
                                                         float* __restrict__ sumpart,
                                                         float* __restrict__ vimg)
{
    int bh = blockIdx.x;
    int j = blockIdx.y;
    int b = bh >> 3, head = bh & 7;
    __shared__ float Ks[32][64];
    __shared__ float Vs[32][68];
    __shared__ float part[4][64];
    int t = threadIdx.x;

    float acc[4][4];
    #pragma unroll
    for (int i = 0; i < 4; i++)
        #pragma unroll
        for (int jj = 0; jj < 4; jj++) acc[i][jj] = 0.f;
    float mysum = 0.f;

    const int rb = (t >> 4) * 4;
    const int cb = (t & 15) * 4;
    const int sr = (t >> 6) * 8;
    const int sc = t & 63;
    const int lane = t & 31;
    const int crow = t >> 5;
    const float* kbase = qkv + (size_t)b * NN_TOK * 1536 + 512 + head * 64;
    const float* vbase = qkv + (size_t)b * NN_TOK * 1536 + 1024 + head * 64;
    float* vrow_base = vimg + ((size_t)(b * CC + head * 64)) * PIX;
    const int nstart = j * KV_CHUNK;
    const int nend = min(nstart + KV_CHUNK, NN_TOK);

    for (int n0 = nstart; n0 < nend; n0 += 32) {
        #pragma unroll
        for (int i = 0; i < 2; i++) {
            int idx = t + i * 256;
            int nn = idx >> 4;
            int c4 = (idx & 15) * 4;
            int n = n0 + nn;
            float4 kk = make_float4(0.f, 0.f, 0.f, 0.f);
            float4 vv = make_float4(0.f, 0.f, 0.f, 0.f);
            if (n < nend) {
                kk = *(const float4*)&kbase[(size_t)n * 1536 + c4];
                vv = *(const float4*)&vbase[(size_t)n * 1536 + c4];
                kk.x = __expf(kk.x); kk.y = __expf(kk.y);
                kk.z = __expf(kk.z); kk.w = __expf(kk.w);
            }
            Ks[nn][c4 + 0] = kk.x; Ks[nn][c4 + 1] = kk.y;
            Ks[nn][c4 + 2] = kk.z; Ks[nn][c4 + 3] = kk.w;
            Vs[nn][c4 + 0] = vv.x; Vs[nn][c4 + 1] = vv.y;
            Vs[nn][c4 + 2] = vv.z; Vs[nn][c4 + 3] = vv.w;
        }
        __syncthreads();
        #pragma unroll
        for (int nn = 0; nn < 32; nn++) {
            float4 k4 = *(const float4*)&Ks[nn][rb];
            float4 v4 = *(const float4*)&Vs[nn][cb];
            float kr[4] = {k4.x, k4.y, k4.z, k4.w};
            float vr[4] = {v4.x, v4.y, v4.z, v4.w};
            #pragma unroll
            for (int i = 0; i < 4; i++)
                #pragma unroll
                for (int jj = 0; jj < 4; jj++)
                    acc[i][jj] = fmaf(kr[i], vr[jj], acc[i][jj]);
        }
        #pragma unroll
        for (int r = 0; r < 8; r++) mysum += Ks[sr + r][sc];
        {
            int n = n0 + lane;
            if (n >= 1 && n < nend) {
                #pragma unroll
                for (int pass = 0; pass < 8; pass++) {
                    int c = crow + pass * 8;
                    vrow_base[(size_t)c * PIX + (n - 1)] = Vs[lane][c];
                }
            }
        }
        __syncthreads();
    }

    part[t >> 6][sc] = mysum;
    __syncthreads();
    if (t < 64)
        sumpart[(bh * KV_CHUNKS + j) * 64 + t] =
            part[0][t] + part[1][t] + part[2][t] + part[3][t];

    float* dst = kvpart + ((size_t)(bh * KV_CHUNKS + j) * 64) * 64;
    #pragma unroll
    for (int i = 0; i < 4; i++)
        *(float4*)&dst[(rb + i) * 64 + cb] =
            make_float4(acc[i][0], acc[i][1], acc[i][2], acc[i][3]);
}

__global__ __launch_bounds__(256) void kv_reduce_kernel(const float* __restrict__ kvpart,
                                                        const float* __restrict__ sumpart,
                                                        float* __restrict__ kvout)
{
    int bh = blockIdx.x;
    int t = threadIdx.x;
    __shared__ float srcp[64];
    if (t < 64) {
        float s = 0.f;
        #pragma unroll
        for (int j = 0; j < KV_CHUNKS; j++)
            s += sumpart[(bh * KV_CHUNKS + j) * 64 + t];
        srcp[t] = 0.125f / s;
    }
    __syncthreads();
    const float* src = kvpart + (size_t)bh * KV_CHUNKS * 4096;
    #pragma unroll
    for (int i = 0; i < 16; i++) {
        int idx = t + i * 256;
        float v = 0.f;
        #pragma unroll
        for (int j = 0; j < KV_CHUNKS; j++)
            v += src[j * 4096 + idx];
        kvout[(size_t)bh * 4096 + idx] = v * srcp[idx >> 6];
    }
}

// ---------------- depthwise conv ----------------
__global__ __launch_bounds__(128) void dwconv_kernel(
    const float* __restrict__ vimg,
    const float* __restrict__ w3, const float* __restrict__ b3,
    const float* __restrict__ w5, const float* __restrict__ b5,
    const float* __restrict__ w7, const float* __restrict__ b7,
    float* __restrict__ convout)
{
    int bc = blockIdx.x;
    int c = bc & 511;
    __shared__ float timg[34 * 34];
    __shared__ float wsm[49];
    int t = threadIdx.x;
    const float* img = vimg + (size_t)bc * PIX;
    for (int i = t; i < 34 * 34; i += 128) {
        int y = i / 34 - 3, x = i % 34 - 3;
        timg[i] = (y >= 0 && y < HH && x >= 0 && x < WW) ? img[y * WW + x] : 0.f;
    }
    int ks; const float* wp; float bias;
    if (c < 128)      { ks = 3; wp = w3 + c * 9;          bias = b3[c]; }
    else if (c < 320) { ks = 5; wp = w5 + (c - 128) * 25; bias = b5[c - 128]; }
    else              { ks = 7; wp = w7 + (c - 320) * 49; bias = b7[c - 320]; }
    if (t < ks * ks) wsm[t] = wp[t];
    __syncthreads();
    int pad = ks >> 1;
    for (int p = t; p < PIX; p += 128) {
        int y = p / WW, x = p % WW;
        float s = bias;
        const int base = (y + 3 - pad) * 34 + (x + 3 - pad);
        for (int ky = 0; ky < ks; ky++)
            for (int kx = 0; kx < ks; kx++)
                s = fmaf(wsm[ky * ks + kx], timg[base + ky * 34 + kx], s);
        convout[(size_t)bc * PIX + p] = s;
    }
}

// ---------------- fused factor_att + crpe + fp16 convert ----------------
__global__ __launch_bounds__(256) void factor_att_fused_kernel(
    const float* __restrict__ qkv, const float* __restrict__ kv,
    const float* __restrict__ conv,
    __half* __restrict__ ah)
{
    int bh = blockIdx.y;
    int b = bh >> 3, head = bh & 7;
    int n0 = blockIdx.x * 64;
    __shared__ float QsT[64][68];
    __shared__ float KVs[64][64];
    __shared__ float CVs[64][65];
    int t = threadIdx.x;

    #pragma unroll
    for (int i = 0; i < 4; i++) {
        int idx = t + i * 256;
        int r = idx >> 4;
        int c4 = (idx & 15) * 4;
        *(float4*)&KVs[r][c4] = *(const float4*)&kv[((size_t)bh * 64 + r) * 64 + c4];
        int n = n0 + r;
        float4 q = make_float4(0.f, 0.f, 0.f, 0.f);
        if (n < NN_TOK)
            q = *(const float4*)&qkv[(size_t)(b * NN_TOK + n) * 1536 + head * 64 + c4];
        QsT[c4 + 0][r] = q.x;
        QsT[c4 + 1][r] = q.y;
        QsT[c4 + 2][r] = q.z;
        QsT[c4 + 3][r] = q.w;
    }
    #pragma unroll
    for (int i = 0; i < 4; i++) {
        int idx = t + i * 256;
        int c = idx >> 4;
        int j4 = (idx & 15) * 4;
        const float* cbase = conv + ((size_t)(b * CC + head * 64 + c)) * PIX;
        #pragma unroll
        for (int k = 0; k < 4; k++) {
            int n = n0 + j4 + k;
            CVs[c][j4 + k] = (n >= 1 && n < NN_TOK) ? cbase[n - 1] : 0.f;
        }
    }
    __syncthreads();

    float acc[4][4];
    #pragma unroll
    for (int i = 0; i < 4; i++)
        #pragma unroll
        for (int j = 0; j < 4; j++) acc[i][j] = 0.f;

    const int rb = (t >> 4) * 4;
    const int cb = (t & 15) * 4;
    #pragma unroll 4
    for (int c = 0; c < 64; c++) {
        float4 q4 = *(const float4*)&QsT[c][rb];
        float4 kv4 = *(const float4*)&KVs[c][cb];
        float qr[4] = {q4.x, q4.y, q4.z, q4.w};
        #pragma unroll
        for (int i = 0; i < 4; i++) {
            acc[i][0] = fmaf(qr[i], kv4.x, acc[i][0]);
            acc[i][1] = fmaf(qr[i], kv4.y, acc[i][1]);
            acc[i][2] = fmaf(qr[i], kv4.z, acc[i][2]);
            acc[i][3] = fmaf(qr[i], kv4.w, acc[i][3]);
        }
    }
    #pragma unroll
    for (int i = 0; i < 4; i++) {
        int n = n0 + rb + i;
        if (n < NN_TOK) {
            size_t base = (size_t)(b * NN_TOK + n) * CC + head * 64 + cb;
            float4 q4 = *(const float4*)&qkv[(size_t)(b * NN_TOK + n) * 1536 + head * 64 + cb];
            float qv[4] = {q4.x, q4.y, q4.z, q4.w};
            float f0 = acc[i][0] + qv[0] * CVs[cb + 0][rb + i];
            float f1 = acc[i][1] + qv[1] * CVs[cb + 1][rb + i];
            float f2 = acc[i][2] + qv[2] * CVs[cb + 2][rb + i];
            float f3 = acc[i][3] + qv[3] * CVs[cb + 3][rb + i];
            *(__half2*)(ah + base)     = __floats2half2_rn(f0, f1);
            *(__half2*)(ah + base + 2) = __floats2half2_rn(f2, f3);
        }
    }
}

// ---------------- launch ----------------
extern "C" void kernel_launch(void* const* d_in, const int* in_sizes, int n_in,
                              void* d_out, int out_size)
{
    const float* x      = (const float*)d_in[0];
    const float* qkv_w  = (const float*)d_in[1];
    const float* qkv_b  = (const float*)d_in[2];
    const float* proj_w = (const float*)d_in[3];
    const float* proj_b = (const float*)d_in[4];
    const float* w3     = (const float*)d_in[5];
    const float* b3     = (const float*)d_in[6];
    const float* w5     = (const float*)d_in[7];
    const float* b5     = (const float*)d_in[8];
    const float* w7     = (const float*)d_in[9];
    const float* b7     = (const float*)d_in[10];
    float* out = (float*)d_out;

    float *qkv, *kv, *kvpart, *sumpart, *vimg, *conv;
    __half *ah, *wh, *ph;
    cudaGetSymbolAddress((void**)&qkv,     g_qkv);
    cudaGetSymbolAddress((void**)&kv,      g_kv);
    cudaGetSymbolAddress((void**)&kvpart,  g_kvpart);
    cudaGetSymbolAddress((void**)&sumpart, g_sumpart);
    cudaGetSymbolAddress((void**)&vimg,    g_vimg);
    cudaGetSymbolAddress((void**)&conv,    g_conv);
    cudaGetSymbolAddress((void**)&ah,      g_ah);
    cudaGetSymbolAddress((void**)&wh,      g_wh);
    cudaGetSymbolAddress((void**)&ph,      g_ph);

    cudaFuncSetAttribute(gemm_mma_kernel,
                         cudaFuncAttributeMaxDynamicSharedMemorySize, GEMM_SMEM);

    const int M = MTOT;
    const int mtiles = (M + Bb - 1) / Bb;   // 197

    // conversions (all plain fp16)
    {
        int n4 = M * KK / 4;
        cvt_kernel<<<(n4 + 255) / 256, 256>>>(x, ah, n4);
        n4 = 1536 * KK / 4;
        cvt_kernel<<<(n4 + 255) / 256, 256>>>(qkv_w, wh, n4);
        n4 = 512 * KK / 4;
        cvt_kernel<<<(n4 + 255) / 256, 256>>>(proj_w, ph, n4);
    }

    // GEMM1: qkv = x @ qkv_w^T + qkv_b
    gemm_mma_kernel<<<dim3(1536 / BN, mtiles), 256, GEMM_SMEM>>>(
        ah, wh, qkv_b, qkv, M, 1536);

    // attention middle
    kv_partial_kernel<<<dim3(256, KV_CHUNKS), 256>>>(qkv, kvpart, sumpart, vimg);
    kv_reduce_kernel<<<256, 256>>>(kvpart, sumpart, kv);
    dwconv_kernel<<<BB * CC, 128>>>(vimg, w3, b3, w5, b5, w7, b7, conv);
    factor_att_fused_kernel<<<dim3((NN_TOK + 63) / 64, 256), 256>>>(
        qkv, kv, conv, ah);

    // GEMM2: out = att @ proj_w^T + proj_b
    gemm_mma_kernel<<<dim3(512 / BN, mtiles), 256, GEMM_SMEM>>>(
        ah, ph, proj_b, out, M, 512);
}